// round 14
// baseline (speedup 1.0000x reference)
#include <cuda_runtime.h>
#include <cuda_fp16.h>
#include <math.h>
#include <stdint.h>

// ---------------- problem constants ----------------
#define BB    4
#define NSEQ  4096
#define NTOK  16384        // BB*NSEQ
#define DIM   1024
#define DH    256
#define SS    256
#define HIDN  32
#define DFF   4096

// ---------------- scratch (device globals: allowed) ----------------
__device__ float g_pinit[NTOK];
__device__ float g_gamma[BB];
__device__ float g_ctxpart[BB * 128 * DIM];
__device__ float g_rowsspart[2 * NTOK];   // psi sum-of-squares partials
__device__ float g_ovsump[2 * NTOK];      // overlap-sum partials
__device__ float g_alpha[NTOK];           // attn row scale (c1/D)
__device__ float g_beta[NTOK];            // attn row offset scale (c0/D)
__device__ float g_votS[DIM];             // colsum of VOT
__device__ float g_bc[512];               // [br | bi]
__device__ float g_VOTpart[4 * DIM * SS]; // split-K fp32 partials
// fp16 GEMM operands (kperm'd where used as GEMM input)
__device__ __half g_h16[NTOK * DIM];
__device__ __half g_psi16[NTOK * 512];    // unnormalized [pr|pi]
__device__ __half g_ov16[NTOK * SS];      // overlap, kperm'd on s
__device__ __half g_h1r16[NTOK * DIM];    // h1, fp16, kperm'd
__device__ __half g_ff116[NTOK * DFF];
__device__ __half g_ao16[NTOK * DIM];     // plain fp16
__device__ __half g_ff216[NTOK * DIM];    // plain fp16
__device__ __half g_WT16[512 * DIM];
__device__ __half g_uw1T16[HIDN * DIM];
__device__ __half g_Mp16[512 * 512];      // INTERLEAVED: row 2s=[Mr|Mi], 2s+1=[Mi|-Mr]
__device__ __half g_owT16[DIM * DIM];
__device__ __half g_val16[SS * DIM];
__device__ __half g_VOT16[DIM * SS];
__device__ __half g_fw1T16[DFF * DIM];
__device__ __half g_fw2T16[DIM * DFF];

// ---------------- helpers ----------------
__device__ __forceinline__ int kperm(int k) {
    int r = k & 31;
    int t = (r >> 1) & 3, w = r >> 4, hh = (r >> 3) & 1, j = r & 1;
    return (k & ~31) | (t << 3) | (w << 2) | (hh << 1) | j;
}

__device__ __forceinline__ float gelu_exact(float x) {
    return 0.5f * x * (1.0f + erff(x * 0.7071067811865475f));
}

__device__ __forceinline__ float block_sum_256(float v) {
    __shared__ float sh[8];
    int lane = threadIdx.x & 31, w = threadIdx.x >> 5;
#pragma unroll
    for (int o = 16; o; o >>= 1) v += __shfl_xor_sync(0xffffffffu, v, o);
    if (lane == 0) sh[w] = v;
    __syncthreads();
    float r = (lane < 8) ? sh[lane] : 0.f;
    if (w == 0) {
#pragma unroll
        for (int o = 4; o; o >>= 1) r += __shfl_xor_sync(0xffffffffu, r, o);
        if (lane == 0) sh[0] = r;
    }
    __syncthreads();
    float out = sh[0];
    __syncthreads();
    return out;
}

__device__ __forceinline__ uint32_t smem_u32(const void* p) {
    return (uint32_t)__cvta_generic_to_shared(p);
}
__device__ __forceinline__ void cp16(uint32_t dst, const void* src) {
    asm volatile("cp.async.cg.shared.global [%0], [%1], 16;" :: "r"(dst), "l"(src));
}
__device__ __forceinline__ void cp_commit() { asm volatile("cp.async.commit_group;"); }
template <int N>
__device__ __forceinline__ void cp_wait() { asm volatile("cp.async.wait_group %0;" :: "n"(N)); }

#define MMA_F16(d, a0, a1, a2, a3, b0, b1) \
    asm volatile( \
        "mma.sync.aligned.m16n8k16.row.col.f32.f16.f16.f32 " \
        "{%0,%1,%2,%3}, {%4,%5,%6,%7}, {%8,%9}, {%0,%1,%2,%3};" \
        : "+f"((d)[0]), "+f"((d)[1]), "+f"((d)[2]), "+f"((d)[3]) \
        : "r"(a0), "r"(a1), "r"(a2), "r"(a3), "r"(b0), "r"(b1))

// ============================================================
// BIG fp16 GEMM: 128 x BN CTA tile, 8 warps, BK = 64 slabs,
// 4-stage cp.async pipeline, prefetch distance 2, ONE sync per 64-k step.
// OMODE: 1 fp16 kperm'd, 2 fp16 plain, 3 fp32 split-K partial,
//        4 overlap: col pairs (re,im) -> ov = re^2+im^2, fp16 kperm'd on s,
//        5 attn-affine: alpha_row*acc + beta_row*S_col + bias_col, fp16 plain.
// SUMSQ: per-row sum partials -> rowss[bx*NTOK+row].
// ============================================================
template <int BN>
__device__ __forceinline__ void load_slab_h(char* smem, int stage,
                                            const __half* gA, const __half* gB,
                                            int k0, int K, int tid) {
    constexpr int STAGE = (128 + BN) * 128;   // 64 halfs/row = 128 B
    uint32_t base = smem_u32(smem) + stage * STAGE;
#pragma unroll
    for (int i = 0; i < 4; i++) {             // A: 128 rows x 8 chunks
        int idx = tid + i * 256;
        int row = idx >> 3, c = idx & 7;
        cp16(base + (uint32_t)(row * 128 + c * 16),
             gA + (size_t)row * K + k0 + c * 8);
    }
    uint32_t bb = base + 128 * 128;
#pragma unroll
    for (int i = 0; i < BN / 32; i++) {       // B: BN rows x 8 chunks
        int idx = tid + i * 256;
        int row = idx >> 3, c = idx & 7;
        cp16(bb + (uint32_t)(row * 128 + c * 16),
             gB + (size_t)row * K + k0 + c * 8);
    }
}

template <int BN, bool GELU, int OMODE, bool SUMSQ>
__global__ __launch_bounds__(256, 1) void hgemm_big(
    const __half* __restrict__ A, const __half* __restrict__ B,
    const float* __restrict__ bias, void* __restrict__ Cv,
    float* __restrict__ rowss,
    const float* __restrict__ rowalpha, const float* __restrict__ rowbeta,
    const float* __restrict__ colS,
    int K, int Ntot, size_t zstride)
{
    extern __shared__ char smem[];
    constexpr int STAGE = (128 + BN) * 128;
    constexpr int NI = BN / 32;

    const int tid = threadIdx.x, wid = tid >> 5, lane = tid & 31;
    const int warp_m = (wid & 1) * 64;
    const int warp_n = (wid >> 1) * (BN / 4);
    const int g = lane >> 2, tg = lane & 3;

    const int kchunk = K / gridDim.z;
    const __half* gA = A + (size_t)blockIdx.y * 128 * K + blockIdx.z * kchunk;
    const __half* gB = B + (size_t)blockIdx.x * BN * K + blockIdx.z * kchunk;
    const int NS = kchunk >> 6;               // 64-k slabs

    float acc[4][NI][4] = {};

    load_slab_h<BN>(smem, 0, gA, gB, 0, K, tid);  cp_commit();
    load_slab_h<BN>(smem, 1, gA, gB, 64, K, tid); cp_commit();

    for (int ks = 0; ks < NS; ks++) {
        if (ks + 2 < NS) {
            load_slab_h<BN>(smem, (ks + 2) & 3, gA, gB, (ks + 2) * 64, K, tid);
            cp_commit();
        }
        int rem = NS - 1 - ks;
        if (rem >= 2) cp_wait<2>();
        else if (rem == 1) cp_wait<1>();
        else cp_wait<0>();
        __syncthreads();

        const __half* As = (const __half*)(smem + (size_t)(ks & 3) * STAGE);
        const __half* Bs = As + 128 * 64;

#pragma unroll
        for (int h2 = 0; h2 < 2; h2++) {
            int ko = h2 * 32 + 8 * tg;
            uint4 aq[4][2];
#pragma unroll
            for (int mi = 0; mi < 4; mi++) {
                aq[mi][0] = *(const uint4*)(As + (warp_m + mi * 16 + g) * 64 + ko);
                aq[mi][1] = *(const uint4*)(As + (warp_m + mi * 16 + 8 + g) * 64 + ko);
            }
            uint4 bq[NI];
#pragma unroll
            for (int ni = 0; ni < NI; ni++)
                bq[ni] = *(const uint4*)(Bs + (warp_n + ni * 8 + g) * 64 + ko);

#pragma unroll
            for (int mi = 0; mi < 4; mi++) {
#pragma unroll
                for (int ni = 0; ni < NI; ni++) {
                    MMA_F16(acc[mi][ni], aq[mi][0].x, aq[mi][1].x, aq[mi][0].y, aq[mi][1].y,
                            bq[ni].x, bq[ni].y);
                    MMA_F16(acc[mi][ni], aq[mi][0].z, aq[mi][1].z, aq[mi][0].w, aq[mi][1].w,
                            bq[ni].z, bq[ni].w);
                }
            }
        }
        // no trailing sync (4-stage, prefetch distance 2)
    }
    __syncthreads();

    float ss[4][2];
    if (SUMSQ) {
#pragma unroll
        for (int mi = 0; mi < 4; mi++) { ss[mi][0] = 0.f; ss[mi][1] = 0.f; }
    }

#pragma unroll
    for (int mi = 0; mi < 4; mi++) {
        int r0 = blockIdx.y * 128 + warp_m + mi * 16 + g;
#pragma unroll
        for (int ni = 0; ni < NI; ni++) {
            int col = blockIdx.x * BN + warp_n + ni * 8 + 2 * tg;
            float bx = 0.f, by = 0.f;
            if ((OMODE == 1 || OMODE == 2 || OMODE == 5) && bias) {
                bx = bias[col]; by = bias[col + 1];
            }
#pragma unroll
            for (int half = 0; half < 2; half++) {
                int row = r0 + half * 8;
                float vx = acc[mi][ni][half * 2 + 0];
                float vy = acc[mi][ni][half * 2 + 1];
                if (OMODE == 4) {
                    float ov = vx * vx + vy * vy;
                    if (SUMSQ) ss[mi][half] += ov;
                    int s = col >> 1;
                    ((__half*)Cv)[(size_t)row * Ntot + kperm(s)] = __float2half_rn(ov);
                    continue;
                }
                if (OMODE == 5) {
                    float al = rowalpha[row], be = rowbeta[row];
                    vx = al * vx + be * colS[col] + bx;
                    vy = al * vy + be * colS[col + 1] + by;
                } else {
                    vx += bx; vy += by;
                }
                if (GELU) { vx = gelu_exact(vx); vy = gelu_exact(vy); }
                if (SUMSQ) ss[mi][half] += vx * vx + vy * vy;
                if (OMODE == 1) {
                    *(__half2*)((__half*)Cv + (size_t)row * Ntot + kperm(col)) =
                        __floats2half2_rn(vx, vy);
                } else if (OMODE == 2 || OMODE == 5) {
                    *(__half2*)((__half*)Cv + (size_t)row * Ntot + col) =
                        __floats2half2_rn(vx, vy);
                } else if (OMODE == 3) {
                    *(float2*)((float*)Cv + blockIdx.z * zstride + (size_t)row * Ntot + col) =
                        make_float2(vx, vy);
                }
            }
        }
    }

    if (SUMSQ) {
        float* red = (float*)smem;   // [128][4]
#pragma unroll
        for (int mi = 0; mi < 4; mi++) {
#pragma unroll
            for (int half = 0; half < 2; half++) {
                float v = ss[mi][half];
                v += __shfl_xor_sync(0xffffffffu, v, 1);
                v += __shfl_xor_sync(0xffffffffu, v, 2);
                if (tg == 0) {
                    int rl = warp_m + mi * 16 + half * 8 + g;
                    red[rl * 4 + (wid >> 1)] = v;
                }
            }
        }
        __syncthreads();
        if (tid < 128) {
            float tot = red[tid * 4] + red[tid * 4 + 1] + red[tid * 4 + 2] + red[tid * 4 + 3];
            rowss[blockIdx.x * NTOK + blockIdx.y * 128 + tid] = tot;
        }
    }
}

// ============================================================
// Gate GEMM (N = 32) with FUSED finish, 6-stage pipeline (BK = 32).
// ============================================================
__device__ __forceinline__ void load_slab_h32(char* smem, int stage,
                                              const __half* gA, const __half* gB,
                                              int k0, int K, int tid) {
    constexpr int STAGE = (128 + 32) * 64;
    uint32_t base = smem_u32(smem) + stage * STAGE;
#pragma unroll
    for (int i = 0; i < 2; i++) {
        int idx = tid + i * 256;
        int row = idx >> 2, c = idx & 3;
        cp16(base + (uint32_t)(row * 64 + c * 16),
             gA + (size_t)row * K + k0 + c * 8);
    }
    uint32_t bb = base + 128 * 64;
    if (tid < 128) {
        int row = tid >> 2, c = tid & 3;
        cp16(bb + (uint32_t)(row * 64 + c * 16),
             gB + (size_t)row * K + k0 + c * 8);
    }
}

__global__ __launch_bounds__(256) void hgemm_gate(
    const __half* __restrict__ A, const __half* __restrict__ B,
    const float* __restrict__ b1, const float* __restrict__ gain,
    const float* __restrict__ beta, const float* __restrict__ w2,
    const float* __restrict__ b2, float* __restrict__ pinit,
    float scale, int K)
{
    extern __shared__ char smem[];
    constexpr int STAGE = (128 + 32) * 64;

    const int tid = threadIdx.x, wid = tid >> 5, lane = tid & 31;
    const int warp_m = wid * 16;
    const int gg2 = lane >> 2, tg = lane & 3;

    const __half* gA = A + (size_t)blockIdx.y * 128 * K;
    const __half* gB = B;
    const int NS = K >> 5;

    float acc[4][4] = {};

#pragma unroll
    for (int s = 0; s < 5; s++) {
        load_slab_h32(smem, s, gA, gB, s * 32, K, tid);
        cp_commit();
    }

    for (int ks = 0; ks < NS; ks++) {
        if (ks + 5 < NS) {
            load_slab_h32(smem, (ks + 5) % 6, gA, gB, (ks + 5) * 32, K, tid);
            cp_commit();
        }
        int rem = NS - 1 - ks;
        if (rem >= 5) cp_wait<5>();
        else if (rem == 4) cp_wait<4>();
        else if (rem == 3) cp_wait<3>();
        else if (rem == 2) cp_wait<2>();
        else if (rem == 1) cp_wait<1>();
        else cp_wait<0>();
        __syncthreads();

        const __half* As = (const __half*)(smem + (size_t)(ks % 6) * STAGE);
        const __half* Bs = As + 128 * 32;

        uint4 alo = *(const uint4*)(As + (warp_m + gg2) * 32 + 8 * tg);
        uint4 ahi = *(const uint4*)(As + (warp_m + 8 + gg2) * 32 + 8 * tg);
        uint4 bq[4];
#pragma unroll
        for (int ni = 0; ni < 4; ni++)
            bq[ni] = *(const uint4*)(Bs + (ni * 8 + gg2) * 32 + 8 * tg);
#pragma unroll
        for (int ni = 0; ni < 4; ni++) {
            MMA_F16(acc[ni], alo.x, ahi.x, alo.y, ahi.y, bq[ni].x, bq[ni].y);
            MMA_F16(acc[ni], alo.z, ahi.z, alo.w, ahi.w, bq[ni].z, bq[ni].w);
        }
        __syncthreads();
    }

#pragma unroll
    for (int half = 0; half < 2; half++) {
        float vv[8];
        float sum = 0.f;
#pragma unroll
        for (int ni = 0; ni < 4; ni++) {
#pragma unroll
            for (int j = 0; j < 2; j++) {
                int col = ni * 8 + 2 * tg + j;
                float v = acc[ni][half * 2 + j] + b1[col];
                vv[ni * 2 + j] = v;
                sum += v;
            }
        }
        sum += __shfl_xor_sync(0xffffffffu, sum, 1);
        sum += __shfl_xor_sync(0xffffffffu, sum, 2);
        float m = sum * (1.f / 32.f);
        float s2 = 0.f;
#pragma unroll
        for (int q = 0; q < 8; q++) { float d = vv[q] - m; s2 += d * d; }
        s2 += __shfl_xor_sync(0xffffffffu, s2, 1);
        s2 += __shfl_xor_sync(0xffffffffu, s2, 2);
        float inv = rsqrtf(s2 * (1.f / 32.f) + 1e-5f);
        float p = 0.f;
#pragma unroll
        for (int ni = 0; ni < 4; ni++) {
#pragma unroll
            for (int j = 0; j < 2; j++) {
                int col = ni * 8 + 2 * tg + j;
                float tn = (vv[ni * 2 + j] - m) * inv * gain[col] + beta[col];
                float si = tn / (1.f + expf(-tn));
                p += si * w2[col];
            }
        }
        p += __shfl_xor_sync(0xffffffffu, p, 1);
        p += __shfl_xor_sync(0xffffffffu, p, 2);
        if (tg == 0) {
            int row = blockIdx.y * 128 + warp_m + half * 8 + gg2;
            pinit[row] = scale / (1.f + expf(-(p + b2[0])));
        }
    }
}

// ============================================================
// PREP megakernel (job table). All blocks 256 threads.
// ============================================================
__device__ __forceinline__ void transpose_tile(const float* in, __half* out,
                                               int R, int C, int lb, int tid) {
    __shared__ float t[32][33];
    int nbx = C >> 5;
    int bx = lb % nbx, by = lb / nbx;
    int c0 = bx * 32, r0 = by * 32;
    int x = tid & 31, y = tid >> 5;
#pragma unroll
    for (int dy = 0; dy < 32; dy += 8)
        t[y + dy][x] = in[(size_t)(r0 + y + dy) * C + c0 + x];
    __syncthreads();
#pragma unroll
    for (int dy = 0; dy < 32; dy += 8)
        out[(size_t)(c0 + y + dy) * R + kperm(r0 + x)] = __float2half_rn(t[x][y + dy]);
}

__global__ void prep_kernel(
    const float* __restrict__ Wr, const float* __restrict__ Wi,
    const float* __restrict__ uw1, const float* __restrict__ ow,
    const float* __restrict__ fw1, const float* __restrict__ fw2,
    const float* __restrict__ values,
    const float* __restrict__ mr, const float* __restrict__ mi,
    const float* __restrict__ br, const float* __restrict__ bi,
    __half* __restrict__ WT16, __half* __restrict__ uw1T16,
    __half* __restrict__ owT16, __half* __restrict__ fw1T16,
    __half* __restrict__ fw2T16, __half* __restrict__ val16,
    __half* __restrict__ Mp16, float* __restrict__ bc)
{
    int b = blockIdx.x, tid = threadIdx.x;
    if (b < 256) { transpose_tile(Wr, WT16, DIM, DH, b, tid); return; }
    b -= 256;
    if (b < 256) { transpose_tile(Wi, WT16 + 256 * DIM, DIM, DH, b, tid); return; }
    b -= 256;
    if (b < 32)  { transpose_tile(uw1, uw1T16, DIM, HIDN, b, tid); return; }
    b -= 32;
    if (b < 1024){ transpose_tile(ow, owT16, DIM, DIM, b, tid); return; }
    b -= 1024;
    if (b < 4096){ transpose_tile(fw1, fw1T16, DIM, DFF, b, tid); return; }
    b -= 4096;
    if (b < 4096){ transpose_tile(fw2, fw2T16, DFF, DIM, b, tid); return; }
    b -= 4096;
    if (b < 256) {
        int i = (b * 256 + tid) * 4;
        float4 v = *(const float4*)(values + i);
        int p0 = kperm(i);
        *(__half2*)(val16 + p0) = __floats2half2_rn(v.x, v.y);
        *(__half2*)(val16 + p0 + 8) = __floats2half2_rn(v.z, v.w);
        return;
    }
    b -= 256;
    if (b < 256) {
        // memnorm -> INTERLEAVED Mp: row 2s = [Mr|Mi], row 2s+1 = [Mi|-Mr]
        int s = b, d = tid;
        float a = mr[s * DH + d], bb2 = mi[s * DH + d];
        float tot = block_sum_256(a * a + bb2 * bb2);
        float inv = 1.f / fmaxf(sqrtf(tot), 1e-12f);
        float ra = a * inv, rb = bb2 * inv;
        Mp16[(size_t)(2 * s) * 512 + kperm(d)] = __float2half_rn(ra);
        Mp16[(size_t)(2 * s) * 512 + kperm(256 + d)] = __float2half_rn(rb);
        Mp16[(size_t)(2 * s + 1) * 512 + kperm(d)] = __float2half_rn(rb);
        Mp16[(size_t)(2 * s + 1) * 512 + kperm(256 + d)] = __float2half_rn(-ra);
        return;
    }
    {
        bc[tid] = br[tid];
        bc[256 + tid] = bi[tid];
    }
}
#define PREP_BLOCKS (256 + 256 + 32 + 1024 + 4096 + 4096 + 256 + 256 + 1)

// ---------------- elementwise kernels ----------------
__global__ void ctx_partial_cvt_kernel(const float* __restrict__ h,
                                       float* __restrict__ part,
                                       __half* __restrict__ h16) {
    int tid = threadIdx.x;
    int d0 = tid * 4;
    int b = blockIdx.y, c = blockIdx.z;
    int p0 = kperm(d0);
    size_t row0 = (size_t)b * NSEQ + c * 32;
    const float* base = h + row0 * DIM;
    float s0 = 0.f, s1 = 0.f, s2 = 0.f, s3 = 0.f;
#pragma unroll 4
    for (int n = 0; n < 32; n++) {
        float4 v = *(const float4*)(base + (size_t)n * DIM + d0);
        s0 += v.x; s1 += v.y; s2 += v.z; s3 += v.w;
        __half* hr = h16 + (row0 + n) * DIM;
        *(__half2*)(hr + p0) = __floats2half2_rn(v.x, v.y);
        *(__half2*)(hr + p0 + 8) = __floats2half2_rn(v.z, v.w);
    }
    *(float4*)(part + (size_t)(b * 128 + c) * DIM + d0) = make_float4(s0, s1, s2, s3);
}

__global__ __launch_bounds__(1024) void ctxgate_kernel(
    const float* __restrict__ part,
    const float* __restrict__ w1, const float* __restrict__ b1,
    const float* __restrict__ gain, const float* __restrict__ beta,
    const float* __restrict__ w2, const float* __restrict__ b2,
    float* __restrict__ gamma)
{
    __shared__ float cs[DIM];
    __shared__ float tj[HIDN];
    int b = blockIdx.x, tid = threadIdx.x;
    int w = tid >> 5, l = tid & 31;

    float s = 0.f;
#pragma unroll
    for (int c = 0; c < 128; c++) s += part[(size_t)(b * 128 + c) * DIM + tid];
    cs[tid] = s * (1.f / (float)NSEQ);
    __syncthreads();

    float acc = 0.f;
#pragma unroll 8
    for (int it = 0; it < DIM / 32; it++) {
        int d = l + it * 32;
        acc += cs[d] * w1[d * HIDN + w];
    }
#pragma unroll
    for (int o = 16; o; o >>= 1) acc += __shfl_xor_sync(0xffffffffu, acc, o);
    if (l == 0) tj[w] = acc + b1[w];
    __syncthreads();

    if (tid < HIDN) {
        float v = tj[tid];
        float m = v;
#pragma unroll
        for (int o = 16; o; o >>= 1) m += __shfl_xor_sync(0xffffffffu, m, o);
        m *= (1.f / 32.f);
        float d = v - m;
        float var = d * d;
#pragma unroll
        for (int o = 16; o; o >>= 1) var += __shfl_xor_sync(0xffffffffu, var, o);
        var *= (1.f / 32.f);
        float tn = d * rsqrtf(var + 1e-5f) * gain[tid] + beta[tid];
        float si = tn / (1.f + expf(-tn));
        float p = si * w2[tid];
#pragma unroll
        for (int o = 16; o; o >>= 1) p += __shfl_xor_sync(0xffffffffu, p, o);
        if (tid == 0) gamma[b] = 1.f / (1.f + expf(-(p + b2[0])));
    }
}

__global__ void cvt_vot_kernel(const float* __restrict__ part, __half* __restrict__ out) {
    int i = (blockIdx.x * 256 + threadIdx.x) * 4;
    const int SZ = DIM * SS;
    float4 a = *(const float4*)(part + i);
    float4 b = *(const float4*)(part + SZ + i);
    float4 c = *(const float4*)(part + 2 * SZ + i);
    float4 d = *(const float4*)(part + 3 * SZ + i);
    float x = a.x + b.x + c.x + d.x;
    float y = a.y + b.y + c.y + d.y;
    float z = a.z + b.z + c.z + d.z;
    float w = a.w + b.w + c.w + d.w;
    int p0 = kperm(i);
    *(__half2*)(out + p0) = __floats2half2_rn(x, y);
    *(__half2*)(out + p0 + 8) = __floats2half2_rn(z, w);
}

// colsum of VOT: warp per d row. grid DIM/8 x 256 (8 warps).
__global__ void votsum_kernel(const __half* __restrict__ VOT16, float* __restrict__ S) {
    int wid = threadIdx.x >> 5, lane = threadIdx.x & 31;
    int d = blockIdx.x * 8 + wid;
    const __half2* r = (const __half2*)(VOT16 + (size_t)d * SS);
    float s = 0.f;
#pragma unroll
    for (int q = 0; q < 4; q++) {
        float2 v = __half22float2(r[lane + q * 32]);
        s += v.x + v.y;
    }
#pragma unroll
    for (int o = 16; o; o >>= 1) s += __shfl_xor_sync(0xffffffffu, s, o);
    if (lane == 0) S[d] = s;
}

// per-row attention affine factors: alpha = c1/D, beta = c0/D
__global__ void rowfac_kernel(const float* __restrict__ pinit, const float* __restrict__ gamma,
                              const float* __restrict__ rowssp, const float* __restrict__ ovsump,
                              float* __restrict__ alpha, float* __restrict__ beta) {
    int row = blockIdx.x * 256 + threadIdx.x;
    int b = row >> 12;
    float p = pinit[row] * (1.f - gamma[b]);
    float n2 = fmaxf(rowssp[row] + rowssp[NTOK + row], 1e-24f);
    float ovs = ovsump[row] + ovsump[NTOK + row];
    float c1 = (1.f - p) / n2;
    float c0 = p * (1.f / (float)DH);
    float D = c1 * ovs + (float)SS * c0 + 1e-8f;
    alpha[row] = c1 / D;
    beta[row] = c0 / D;
}

// mid LN: h1 = LN(h16 + ao16); writes ONLY fp16 kperm'd copy
__global__ void ln_add_mid_kernel(const __half* __restrict__ a, const __half* __restrict__ bsrc,
                                  const float* __restrict__ g, const float* __restrict__ beta,
                                  __half* __restrict__ outr) {
    size_t off = (size_t)blockIdx.x * DIM;
    int tid = threadIdx.x;
    float v[4];
    float s = 0.f;
#pragma unroll
    for (int q = 0; q < 4; q++) {
        int i = tid + q * 256;
        v[q] = __half2float(a[off + kperm(i)]) + __half2float(bsrc[off + i]);
        s += v[q];
    }
    float mu = block_sum_256(s) * (1.f / (float)DIM);
    float s2 = 0.f;
#pragma unroll
    for (int q = 0; q < 4; q++) {
        float d = v[q] - mu;
        s2 += d * d;
    }
    float var = block_sum_256(s2) * (1.f / (float)DIM);
    float inv = rsqrtf(var + 1e-5f);
#pragma unroll
    for (int q = 0; q < 4; q++) {
        int i = tid + q * 256;
        float o = (v[q] - mu) * inv * g[i] + beta[i];
        outr[off + kperm(i)] = __float2half_rn(o);
    }
}

// final LN: out = LN(h1r16[kperm] + ff216)
__global__ void ln_add_final_kernel(const __half* __restrict__ a, const __half* __restrict__ bsrc,
                                    const float* __restrict__ g, const float* __restrict__ beta,
                                    float* __restrict__ out) {
    size_t off = (size_t)blockIdx.x * DIM;
    int tid = threadIdx.x;
    float v[4];
    float s = 0.f;
#pragma unroll
    for (int q = 0; q < 4; q++) {
        int i = tid + q * 256;
        v[q] = __half2float(a[off + kperm(i)]) + __half2float(bsrc[off + i]);
        s += v[q];
    }
    float mu = block_sum_256(s) * (1.f / (float)DIM);
    float s2 = 0.f;
#pragma unroll
    for (int q = 0; q < 4; q++) {
        float d = v[q] - mu;
        s2 += d * d;
    }
    float var = block_sum_256(s2) * (1.f / (float)DIM);
    float inv = rsqrtf(var + 1e-5f);
#pragma unroll
    for (int q = 0; q < 4; q++) {
        int i = tid + q * 256;
        out[off + i] = (v[q] - mu) * inv * g[i] + beta[i];
    }
}

// ---------------- launch ----------------
static inline void* symv(const void* s) {
    void* p = nullptr;
    cudaGetSymbolAddress(&p, s);
    return p;
}

extern "C" void kernel_launch(void* const* d_in, const int* in_sizes, int n_in,
                              void* d_out, int out_size) {
    const float* h     = (const float*)d_in[0];
    const float* Wr    = (const float*)d_in[1];
    const float* br    = (const float*)d_in[2];
    const float* Wi    = (const float*)d_in[3];
    const float* bi    = (const float*)d_in[4];
    const float* uw1   = (const float*)d_in[5];
    const float* ub1   = (const float*)d_in[6];
    const float* ug    = (const float*)d_in[7];
    const float* ubeta = (const float*)d_in[8];
    const float* uw2   = (const float*)d_in[9];
    const float* ub2   = (const float*)d_in[10];
    const float* gw1   = (const float*)d_in[11];
    const float* gb1   = (const float*)d_in[12];
    const float* gg    = (const float*)d_in[13];
    const float* gbeta = (const float*)d_in[14];
    const float* gw2   = (const float*)d_in[15];
    const float* gb2   = (const float*)d_in[16];
    const float* m_real= (const float*)d_in[17];
    const float* m_imag= (const float*)d_in[18];
    const float* values= (const float*)d_in[19];
    const float* ow    = (const float*)d_in[20];
    const float* ob    = (const float*)d_in[21];
    const float* n1g   = (const float*)d_in[22];
    const float* n1b   = (const float*)d_in[23];
    const float* n2g   = (const float*)d_in[24];
    const float* n2b   = (const float*)d_in[25];
    const float* fw1   = (const float*)d_in[26];
    const float* fb1   = (const float*)d_in[27];
    const float* fw2   = (const float*)d_in[28];
    const float* fb2   = (const float*)d_in[29];
    float* out = (float*)d_out;

    float* pinit = (float*)symv(g_pinit);
    float* gam   = (float*)symv(g_gamma);
    float* ctxp  = (float*)symv(g_ctxpart);
    float* rowssp= (float*)symv(g_rowsspart);
    float* ovsump= (float*)symv(g_ovsump);
    float* alpha = (float*)symv(g_alpha);
    float* beta  = (float*)symv(g_beta);
    float* votS  = (float*)symv(g_votS);
    float* bc    = (float*)symv(g_bc);
    float* VOTp  = (float*)symv(g_VOTpart);
    __half* h16    = (__half*)symv(g_h16);
    __half* psi16  = (__half*)symv(g_psi16);
    __half* ov16   = (__half*)symv(g_ov16);
    __half* h1r16  = (__half*)symv(g_h1r16);
    __half* ff116  = (__half*)symv(g_ff116);
    __half* ao16   = (__half*)symv(g_ao16);
    __half* ff216  = (__half*)symv(g_ff216);
    __half* WT16   = (__half*)symv(g_WT16);
    __half* uw1T16 = (__half*)symv(g_uw1T16);
    __half* Mp16   = (__half*)symv(g_Mp16);
    __half* owT16  = (__half*)symv(g_owT16);
    __half* val16  = (__half*)symv(g_val16);
    __half* VOT16  = (__half*)symv(g_VOT16);
    __half* fw1T16 = (__half*)symv(g_fw1T16);
    __half* fw2T16 = (__half*)symv(g_fw2T16);

    const int smBIG  = (128 + 256) * 128 * 4;   // 196608
    const int smBIG1 = (128 + 128) * 128 * 4;   // 131072
    const int smGATE = (128 + 32) * 64 * 6;     // 61440
    cudaFuncSetAttribute(hgemm_big<256, false, 1, true >, cudaFuncAttributeMaxDynamicSharedMemorySize, smBIG);
    cudaFuncSetAttribute(hgemm_big<256, false, 3, false>, cudaFuncAttributeMaxDynamicSharedMemorySize, smBIG);
    cudaFuncSetAttribute(hgemm_big<256, false, 4, true >, cudaFuncAttributeMaxDynamicSharedMemorySize, smBIG);
    cudaFuncSetAttribute(hgemm_big<256, false, 5, false>, cudaFuncAttributeMaxDynamicSharedMemorySize, smBIG);
    cudaFuncSetAttribute(hgemm_big<256, true,  1, false>, cudaFuncAttributeMaxDynamicSharedMemorySize, smBIG);
    cudaFuncSetAttribute(hgemm_big<128, false, 2, false>, cudaFuncAttributeMaxDynamicSharedMemorySize, smBIG1);
    cudaFuncSetAttribute(hgemm_gate, cudaFuncAttributeMaxDynamicSharedMemorySize, smGATE);

    // fork-join streams/events (created once, outside capture on first call)
    static cudaStream_t s1 = nullptr, s2 = nullptr;
    static cudaEvent_t evEntry = nullptr, evPrep = nullptr, evCtx = nullptr,
                       evGate = nullptr, evVot = nullptr;
    if (!s1) {
        cudaStreamCreateWithFlags(&s1, cudaStreamNonBlocking);
        cudaStreamCreateWithFlags(&s2, cudaStreamNonBlocking);
        cudaEventCreateWithFlags(&evEntry, cudaEventDisableTiming);
        cudaEventCreateWithFlags(&evPrep, cudaEventDisableTiming);
        cudaEventCreateWithFlags(&evCtx, cudaEventDisableTiming);
        cudaEventCreateWithFlags(&evGate, cudaEventDisableTiming);
        cudaEventCreateWithFlags(&evVot, cudaEventDisableTiming);
    }

    dim3 thr(256);

    // fork s2: weight prep + VOT chain + colsum
    cudaEventRecord(evEntry, 0);
    cudaStreamWaitEvent(s2, evEntry, 0);
    prep_kernel<<<PREP_BLOCKS, thr, 0, s2>>>(Wr, Wi, uw1, ow, fw1, fw2, values,
                                             m_real, m_imag, br, bi,
                                             WT16, uw1T16, owT16, fw1T16, fw2T16,
                                             val16, Mp16, bc);
    cudaEventRecord(evPrep, s2);
    hgemm_big<256, false, 3, false><<<dim3(1, 8, 4), thr, smBIG, s2>>>(
        owT16, val16, nullptr, VOTp, nullptr, nullptr, nullptr, nullptr,
        DIM, SS, (size_t)DIM * SS);
    cvt_vot_kernel<<<DIM * SS / 1024, thr, 0, s2>>>(VOTp, VOT16);
    votsum_kernel<<<DIM / 8, thr, 0, s2>>>(VOT16, votS);
    cudaEventRecord(evVot, s2);

    // main: ctx partials + h -> h16 (overlaps prep)
    ctx_partial_cvt_kernel<<<dim3(1, BB, 128), thr>>>(h, ctxp, h16);
    cudaEventRecord(evCtx, 0);

    // s1: gamma gate + uncertainty gate (overlap psi/ov on main)
    cudaStreamWaitEvent(s1, evCtx, 0);
    cudaStreamWaitEvent(s1, evPrep, 0);
    ctxgate_kernel<<<BB, 1024, 0, s1>>>(ctxp, gw1, gb1, gg, gbeta, gw2, gb2, gam);
    hgemm_gate<<<dim3(1, 128), thr, smGATE, s1>>>(h16, uw1T16, ub1, ug, ubeta, uw2, ub2,
                                                  pinit, 0.95f, DIM);
    cudaEventRecord(evGate, s1);

    // main: psi (kperm'd + rowss partials) -> ov (overlap + ovsum partials)
    cudaStreamWaitEvent(0, evPrep, 0);
    hgemm_big<256, false, 1, true><<<dim3(2, 128), thr, smBIG>>>(
        h16, WT16, bc, psi16, rowssp, nullptr, nullptr, nullptr, DIM, 512, 0);
    hgemm_big<256, false, 4, true><<<dim3(2, 128), thr, smBIG>>>(
        psi16, Mp16, nullptr, ov16, ovsump, nullptr, nullptr, nullptr, 512, SS, 0);

    // join gate, then per-row attention factors
    cudaStreamWaitEvent(0, evGate, 0);
    rowfac_kernel<<<NTOK / 256, thr>>>(pinit, gam, rowssp, ovsump, alpha, beta);

    // join VOT, then ao = alpha*(ov @ VOT^T) + beta*S + ob   (fp16 plain)
    cudaStreamWaitEvent(0, evVot, 0);
    hgemm_big<256, false, 5, false><<<dim3(4, 128), thr, smBIG>>>(
        ov16, VOT16, ob, ao16, nullptr, alpha, beta, votS, SS, DIM, 0);

    // h1 = LN(h16 + ao16) -> fp16 kperm'd only
    ln_add_mid_kernel<<<NTOK, 256>>>(h16, ao16, n1g, n1b, h1r16);

    // FFN
    hgemm_big<256, true, 1, false><<<dim3(16, 128), thr, smBIG>>>(
        h1r16, fw1T16, fb1, ff116, nullptr, nullptr, nullptr, nullptr, DIM, DFF, 0);
    hgemm_big<128, false, 2, false><<<dim3(8, 128), thr, smBIG1>>>(
        ff116, fw2T16, fb2, ff216, nullptr, nullptr, nullptr, nullptr, DFF, DIM, 0);

    // out = LN(h1 + ff2)
    ln_add_final_kernel<<<NTOK, 256>>>(h1r16, ff216, n2g, n2b, out);
}

// round 15
// speedup vs baseline: 1.1336x; 1.1336x over previous
#include <cuda_runtime.h>
#include <cuda_fp16.h>
#include <math.h>
#include <stdint.h>

// ---------------- problem constants ----------------
#define BB    4
#define NSEQ  4096
#define NTOK  16384        // BB*NSEQ
#define DIM   1024
#define DH    256
#define SS    256
#define HIDN  32
#define DFF   4096

// ---------------- scratch (device globals: allowed) ----------------
__device__ float g_pinit[NTOK];
__device__ float g_gamma[BB];
__device__ float g_ctxpart[BB * 128 * DIM];
__device__ float g_rowsspart[2 * NTOK];   // psi sum-of-squares partials
__device__ float g_ovsump[2 * NTOK];      // overlap-sum partials
__device__ float g_alpha[NTOK];           // attn row scale (c1/D)
__device__ float g_beta[NTOK];            // attn row offset scale (c0/D)
__device__ float g_votS[DIM];             // colsum of VOT
__device__ float g_bc[512];               // [br | bi]
__device__ float g_VOTpart[4 * DIM * SS]; // split-K fp32 partials
// fp16 GEMM operands (kperm'd where used as GEMM input)
__device__ __half g_h16[NTOK * DIM];
__device__ __half g_psi16[NTOK * 512];    // unnormalized [pr|pi]
__device__ __half g_ov16[NTOK * SS];      // overlap, kperm'd on s
__device__ __half g_h1r16[NTOK * DIM];    // h1, fp16, kperm'd
__device__ __half g_ff116[NTOK * DFF];
__device__ __half g_ao16[NTOK * DIM];     // plain fp16
__device__ __half g_ff216[NTOK * DIM];    // plain fp16
__device__ __half g_WT16[512 * DIM];
__device__ __half g_uw1T16[HIDN * DIM];
__device__ __half g_Mp16[512 * 512];      // INTERLEAVED: row 2s=[Mr|Mi], 2s+1=[Mi|-Mr]
__device__ __half g_owT16[DIM * DIM];
__device__ __half g_val16[SS * DIM];
__device__ __half g_VOT16[DIM * SS];
__device__ __half g_fw1T16[DFF * DIM];
__device__ __half g_fw2T16[DIM * DFF];

// ---------------- helpers ----------------
__device__ __forceinline__ int kperm(int k) {
    int r = k & 31;
    int t = (r >> 1) & 3, w = r >> 4, hh = (r >> 3) & 1, j = r & 1;
    return (k & ~31) | (t << 3) | (w << 2) | (hh << 1) | j;
}

__device__ __forceinline__ float gelu_exact(float x) {
    return 0.5f * x * (1.0f + erff(x * 0.7071067811865475f));
}

__device__ __forceinline__ float block_sum_256(float v) {
    __shared__ float sh[8];
    int lane = threadIdx.x & 31, w = threadIdx.x >> 5;
#pragma unroll
    for (int o = 16; o; o >>= 1) v += __shfl_xor_sync(0xffffffffu, v, o);
    if (lane == 0) sh[w] = v;
    __syncthreads();
    float r = (lane < 8) ? sh[lane] : 0.f;
    if (w == 0) {
#pragma unroll
        for (int o = 4; o; o >>= 1) r += __shfl_xor_sync(0xffffffffu, r, o);
        if (lane == 0) sh[0] = r;
    }
    __syncthreads();
    float out = sh[0];
    __syncthreads();
    return out;
}

__device__ __forceinline__ uint32_t smem_u32(const void* p) {
    return (uint32_t)__cvta_generic_to_shared(p);
}
__device__ __forceinline__ void cp16(uint32_t dst, const void* src) {
    asm volatile("cp.async.cg.shared.global [%0], [%1], 16;" :: "r"(dst), "l"(src));
}
__device__ __forceinline__ void cp_commit() { asm volatile("cp.async.commit_group;"); }
template <int N>
__device__ __forceinline__ void cp_wait() { asm volatile("cp.async.wait_group %0;" :: "n"(N)); }

#define MMA_F16(d, a0, a1, a2, a3, b0, b1) \
    asm volatile( \
        "mma.sync.aligned.m16n8k16.row.col.f32.f16.f16.f32 " \
        "{%0,%1,%2,%3}, {%4,%5,%6,%7}, {%8,%9}, {%0,%1,%2,%3};" \
        : "+f"((d)[0]), "+f"((d)[1]), "+f"((d)[2]), "+f"((d)[3]) \
        : "r"(a0), "r"(a1), "r"(a2), "r"(a3), "r"(b0), "r"(b1))

// ============================================================
// BIG fp16 GEMM: 128 x BN CTA tile, 8 warps, BK = 64 slabs,
// 4-stage cp.async pipeline, prefetch distance 2, ONE sync per 64-k step.
// SMEM rows = 64 halfs (128 B); chunk swizzle p = c ^ ((row&1)<<2) makes
// both cp.async writes and LDS.128 fragment reads bank-conflict-free
// (quarter-warp phase covers rows of both parities -> 8 distinct chunks).
// OMODE: 1 fp16 kperm'd, 2 fp16 plain, 3 fp32 split-K partial,
//        4 overlap: col pairs (re,im) -> ov = re^2+im^2, fp16 kperm'd on s,
//        5 attn-affine: alpha_row*acc + beta_row*S_col + bias_col, fp16 plain.
// SUMSQ: per-row sum partials -> rowss[bx*NTOK+row].
// ============================================================
template <int BN>
__device__ __forceinline__ void load_slab_h(char* smem, int stage,
                                            const __half* gA, const __half* gB,
                                            int k0, int K, int tid) {
    constexpr int STAGE = (128 + BN) * 128;   // 64 halfs/row = 128 B
    uint32_t base = smem_u32(smem) + stage * STAGE;
#pragma unroll
    for (int i = 0; i < 4; i++) {             // A: 128 rows x 8 chunks
        int idx = tid + i * 256;
        int row = idx >> 3, c = idx & 7;
        int p = c ^ ((row & 1) << 2);
        cp16(base + (uint32_t)(row * 128 + p * 16),
             gA + (size_t)row * K + k0 + c * 8);
    }
    uint32_t bb = base + 128 * 128;
#pragma unroll
    for (int i = 0; i < BN / 32; i++) {       // B: BN rows x 8 chunks
        int idx = tid + i * 256;
        int row = idx >> 3, c = idx & 7;
        int p = c ^ ((row & 1) << 2);
        cp16(bb + (uint32_t)(row * 128 + p * 16),
             gB + (size_t)row * K + k0 + c * 8);
    }
}

template <int BN, bool GELU, int OMODE, bool SUMSQ>
__global__ __launch_bounds__(256, 1) void hgemm_big(
    const __half* __restrict__ A, const __half* __restrict__ B,
    const float* __restrict__ bias, void* __restrict__ Cv,
    float* __restrict__ rowss,
    const float* __restrict__ rowalpha, const float* __restrict__ rowbeta,
    const float* __restrict__ colS,
    int K, int Ntot, size_t zstride)
{
    extern __shared__ char smem[];
    constexpr int STAGE = (128 + BN) * 128;
    constexpr int NI = BN / 32;

    const int tid = threadIdx.x, wid = tid >> 5, lane = tid & 31;
    const int warp_m = (wid & 1) * 64;
    const int warp_n = (wid >> 1) * (BN / 4);
    const int g = lane >> 2, tg = lane & 3;
    const int psw = (g & 1) << 2;             // row-parity swizzle for fragments

    const int kchunk = K / gridDim.z;
    const __half* gA = A + (size_t)blockIdx.y * 128 * K + blockIdx.z * kchunk;
    const __half* gB = B + (size_t)blockIdx.x * BN * K + blockIdx.z * kchunk;
    const int NS = kchunk >> 6;               // 64-k slabs

    float acc[4][NI][4] = {};

    load_slab_h<BN>(smem, 0, gA, gB, 0, K, tid);  cp_commit();
    load_slab_h<BN>(smem, 1, gA, gB, 64, K, tid); cp_commit();

    for (int ks = 0; ks < NS; ks++) {
        if (ks + 2 < NS) {
            load_slab_h<BN>(smem, (ks + 2) & 3, gA, gB, (ks + 2) * 64, K, tid);
            cp_commit();
        }
        int rem = NS - 1 - ks;
        if (rem >= 2) cp_wait<2>();
        else if (rem == 1) cp_wait<1>();
        else cp_wait<0>();
        __syncthreads();

        const __half* As = (const __half*)(smem + (size_t)(ks & 3) * STAGE);
        const __half* Bs = As + 128 * 64;

#pragma unroll
        for (int h2 = 0; h2 < 2; h2++) {
            int chunk = h2 * 4 + tg;
            int ko = (chunk ^ psw) * 8;       // physical halfs offset in row
            uint4 aq[4][2];
#pragma unroll
            for (int mi = 0; mi < 4; mi++) {
                aq[mi][0] = *(const uint4*)(As + (warp_m + mi * 16 + g) * 64 + ko);
                aq[mi][1] = *(const uint4*)(As + (warp_m + mi * 16 + 8 + g) * 64 + ko);
            }
            uint4 bq[NI];
#pragma unroll
            for (int ni = 0; ni < NI; ni++)
                bq[ni] = *(const uint4*)(Bs + (warp_n + ni * 8 + g) * 64 + ko);

#pragma unroll
            for (int mi = 0; mi < 4; mi++) {
#pragma unroll
                for (int ni = 0; ni < NI; ni++) {
                    MMA_F16(acc[mi][ni], aq[mi][0].x, aq[mi][1].x, aq[mi][0].y, aq[mi][1].y,
                            bq[ni].x, bq[ni].y);
                    MMA_F16(acc[mi][ni], aq[mi][0].z, aq[mi][1].z, aq[mi][0].w, aq[mi][1].w,
                            bq[ni].z, bq[ni].w);
                }
            }
        }
        // no trailing sync (4-stage, prefetch distance 2)
    }
    __syncthreads();

    float ss[4][2];
    if (SUMSQ) {
#pragma unroll
        for (int mi = 0; mi < 4; mi++) { ss[mi][0] = 0.f; ss[mi][1] = 0.f; }
    }

#pragma unroll
    for (int mi = 0; mi < 4; mi++) {
        int r0 = blockIdx.y * 128 + warp_m + mi * 16 + g;
#pragma unroll
        for (int ni = 0; ni < NI; ni++) {
            int col = blockIdx.x * BN + warp_n + ni * 8 + 2 * tg;
            float bx = 0.f, by = 0.f;
            if ((OMODE == 1 || OMODE == 2 || OMODE == 5) && bias) {
                bx = bias[col]; by = bias[col + 1];
            }
#pragma unroll
            for (int half = 0; half < 2; half++) {
                int row = r0 + half * 8;
                float vx = acc[mi][ni][half * 2 + 0];
                float vy = acc[mi][ni][half * 2 + 1];
                if (OMODE == 4) {
                    float ov = vx * vx + vy * vy;
                    if (SUMSQ) ss[mi][half] += ov;
                    int s = col >> 1;
                    ((__half*)Cv)[(size_t)row * Ntot + kperm(s)] = __float2half_rn(ov);
                    continue;
                }
                if (OMODE == 5) {
                    float al = rowalpha[row], be = rowbeta[row];
                    vx = al * vx + be * colS[col] + bx;
                    vy = al * vy + be * colS[col + 1] + by;
                } else {
                    vx += bx; vy += by;
                }
                if (GELU) { vx = gelu_exact(vx); vy = gelu_exact(vy); }
                if (SUMSQ) ss[mi][half] += vx * vx + vy * vy;
                if (OMODE == 1) {
                    *(__half2*)((__half*)Cv + (size_t)row * Ntot + kperm(col)) =
                        __floats2half2_rn(vx, vy);
                } else if (OMODE == 2 || OMODE == 5) {
                    *(__half2*)((__half*)Cv + (size_t)row * Ntot + col) =
                        __floats2half2_rn(vx, vy);
                } else if (OMODE == 3) {
                    *(float2*)((float*)Cv + blockIdx.z * zstride + (size_t)row * Ntot + col) =
                        make_float2(vx, vy);
                }
            }
        }
    }

    if (SUMSQ) {
        float* red = (float*)smem;   // [128][4]
#pragma unroll
        for (int mi = 0; mi < 4; mi++) {
#pragma unroll
            for (int half = 0; half < 2; half++) {
                float v = ss[mi][half];
                v += __shfl_xor_sync(0xffffffffu, v, 1);
                v += __shfl_xor_sync(0xffffffffu, v, 2);
                if (tg == 0) {
                    int rl = warp_m + mi * 16 + half * 8 + g;
                    red[rl * 4 + (wid >> 1)] = v;
                }
            }
        }
        __syncthreads();
        if (tid < 128) {
            float tot = red[tid * 4] + red[tid * 4 + 1] + red[tid * 4 + 2] + red[tid * 4 + 3];
            rowss[blockIdx.x * NTOK + blockIdx.y * 128 + tid] = tot;
        }
    }
}

// ============================================================
// Gate GEMM (N = 32) with FUSED finish, 6-stage pipeline (BK = 32).
// ============================================================
__device__ __forceinline__ void load_slab_h32(char* smem, int stage,
                                              const __half* gA, const __half* gB,
                                              int k0, int K, int tid) {
    constexpr int STAGE = (128 + 32) * 64;
    uint32_t base = smem_u32(smem) + stage * STAGE;
#pragma unroll
    for (int i = 0; i < 2; i++) {
        int idx = tid + i * 256;
        int row = idx >> 2, c = idx & 3;
        cp16(base + (uint32_t)(row * 64 + c * 16),
             gA + (size_t)row * K + k0 + c * 8);
    }
    uint32_t bb = base + 128 * 64;
    if (tid < 128) {
        int row = tid >> 2, c = tid & 3;
        cp16(bb + (uint32_t)(row * 64 + c * 16),
             gB + (size_t)row * K + k0 + c * 8);
    }
}

__global__ __launch_bounds__(256) void hgemm_gate(
    const __half* __restrict__ A, const __half* __restrict__ B,
    const float* __restrict__ b1, const float* __restrict__ gain,
    const float* __restrict__ beta, const float* __restrict__ w2,
    const float* __restrict__ b2, float* __restrict__ pinit,
    float scale, int K)
{
    extern __shared__ char smem[];
    constexpr int STAGE = (128 + 32) * 64;

    const int tid = threadIdx.x, wid = tid >> 5, lane = tid & 31;
    const int warp_m = wid * 16;
    const int gg2 = lane >> 2, tg = lane & 3;

    const __half* gA = A + (size_t)blockIdx.y * 128 * K;
    const __half* gB = B;
    const int NS = K >> 5;

    float acc[4][4] = {};

#pragma unroll
    for (int s = 0; s < 5; s++) {
        load_slab_h32(smem, s, gA, gB, s * 32, K, tid);
        cp_commit();
    }

    for (int ks = 0; ks < NS; ks++) {
        if (ks + 5 < NS) {
            load_slab_h32(smem, (ks + 5) % 6, gA, gB, (ks + 5) * 32, K, tid);
            cp_commit();
        }
        int rem = NS - 1 - ks;
        if (rem >= 5) cp_wait<5>();
        else if (rem == 4) cp_wait<4>();
        else if (rem == 3) cp_wait<3>();
        else if (rem == 2) cp_wait<2>();
        else if (rem == 1) cp_wait<1>();
        else cp_wait<0>();
        __syncthreads();

        const __half* As = (const __half*)(smem + (size_t)(ks % 6) * STAGE);
        const __half* Bs = As + 128 * 32;

        uint4 alo = *(const uint4*)(As + (warp_m + gg2) * 32 + 8 * tg);
        uint4 ahi = *(const uint4*)(As + (warp_m + 8 + gg2) * 32 + 8 * tg);
        uint4 bq[4];
#pragma unroll
        for (int ni = 0; ni < 4; ni++)
            bq[ni] = *(const uint4*)(Bs + (ni * 8 + gg2) * 32 + 8 * tg);
#pragma unroll
        for (int ni = 0; ni < 4; ni++) {
            MMA_F16(acc[ni], alo.x, ahi.x, alo.y, ahi.y, bq[ni].x, bq[ni].y);
            MMA_F16(acc[ni], alo.z, ahi.z, alo.w, ahi.w, bq[ni].z, bq[ni].w);
        }
        __syncthreads();
    }

#pragma unroll
    for (int half = 0; half < 2; half++) {
        float vv[8];
        float sum = 0.f;
#pragma unroll
        for (int ni = 0; ni < 4; ni++) {
#pragma unroll
            for (int j = 0; j < 2; j++) {
                int col = ni * 8 + 2 * tg + j;
                float v = acc[ni][half * 2 + j] + b1[col];
                vv[ni * 2 + j] = v;
                sum += v;
            }
        }
        sum += __shfl_xor_sync(0xffffffffu, sum, 1);
        sum += __shfl_xor_sync(0xffffffffu, sum, 2);
        float m = sum * (1.f / 32.f);
        float s2 = 0.f;
#pragma unroll
        for (int q = 0; q < 8; q++) { float d = vv[q] - m; s2 += d * d; }
        s2 += __shfl_xor_sync(0xffffffffu, s2, 1);
        s2 += __shfl_xor_sync(0xffffffffu, s2, 2);
        float inv = rsqrtf(s2 * (1.f / 32.f) + 1e-5f);
        float p = 0.f;
#pragma unroll
        for (int ni = 0; ni < 4; ni++) {
#pragma unroll
            for (int j = 0; j < 2; j++) {
                int col = ni * 8 + 2 * tg + j;
                float tn = (vv[ni * 2 + j] - m) * inv * gain[col] + beta[col];
                float si = tn / (1.f + expf(-tn));
                p += si * w2[col];
            }
        }
        p += __shfl_xor_sync(0xffffffffu, p, 1);
        p += __shfl_xor_sync(0xffffffffu, p, 2);
        if (tg == 0) {
            int row = blockIdx.y * 128 + warp_m + half * 8 + gg2;
            pinit[row] = scale / (1.f + expf(-(p + b2[0])));
        }
    }
}

// ============================================================
// PREP megakernel (job table). All blocks 256 threads.
// ============================================================
__device__ __forceinline__ void transpose_tile(const float* in, __half* out,
                                               int R, int C, int lb, int tid) {
    __shared__ float t[32][33];
    int nbx = C >> 5;
    int bx = lb % nbx, by = lb / nbx;
    int c0 = bx * 32, r0 = by * 32;
    int x = tid & 31, y = tid >> 5;
#pragma unroll
    for (int dy = 0; dy < 32; dy += 8)
        t[y + dy][x] = in[(size_t)(r0 + y + dy) * C + c0 + x];
    __syncthreads();
#pragma unroll
    for (int dy = 0; dy < 32; dy += 8)
        out[(size_t)(c0 + y + dy) * R + kperm(r0 + x)] = __float2half_rn(t[x][y + dy]);
}

__global__ void prep_kernel(
    const float* __restrict__ Wr, const float* __restrict__ Wi,
    const float* __restrict__ uw1, const float* __restrict__ ow,
    const float* __restrict__ fw1, const float* __restrict__ fw2,
    const float* __restrict__ values,
    const float* __restrict__ mr, const float* __restrict__ mi,
    const float* __restrict__ br, const float* __restrict__ bi,
    __half* __restrict__ WT16, __half* __restrict__ uw1T16,
    __half* __restrict__ owT16, __half* __restrict__ fw1T16,
    __half* __restrict__ fw2T16, __half* __restrict__ val16,
    __half* __restrict__ Mp16, float* __restrict__ bc)
{
    int b = blockIdx.x, tid = threadIdx.x;
    if (b < 256) { transpose_tile(Wr, WT16, DIM, DH, b, tid); return; }
    b -= 256;
    if (b < 256) { transpose_tile(Wi, WT16 + 256 * DIM, DIM, DH, b, tid); return; }
    b -= 256;
    if (b < 32)  { transpose_tile(uw1, uw1T16, DIM, HIDN, b, tid); return; }
    b -= 32;
    if (b < 1024){ transpose_tile(ow, owT16, DIM, DIM, b, tid); return; }
    b -= 1024;
    if (b < 4096){ transpose_tile(fw1, fw1T16, DIM, DFF, b, tid); return; }
    b -= 4096;
    if (b < 4096){ transpose_tile(fw2, fw2T16, DFF, DIM, b, tid); return; }
    b -= 4096;
    if (b < 256) {
        int i = (b * 256 + tid) * 4;
        float4 v = *(const float4*)(values + i);
        int p0 = kperm(i);
        *(__half2*)(val16 + p0) = __floats2half2_rn(v.x, v.y);
        *(__half2*)(val16 + p0 + 8) = __floats2half2_rn(v.z, v.w);
        return;
    }
    b -= 256;
    if (b < 256) {
        // memnorm -> INTERLEAVED Mp: row 2s = [Mr|Mi], row 2s+1 = [Mi|-Mr]
        int s = b, d = tid;
        float a = mr[s * DH + d], bb2 = mi[s * DH + d];
        float tot = block_sum_256(a * a + bb2 * bb2);
        float inv = 1.f / fmaxf(sqrtf(tot), 1e-12f);
        float ra = a * inv, rb = bb2 * inv;
        Mp16[(size_t)(2 * s) * 512 + kperm(d)] = __float2half_rn(ra);
        Mp16[(size_t)(2 * s) * 512 + kperm(256 + d)] = __float2half_rn(rb);
        Mp16[(size_t)(2 * s + 1) * 512 + kperm(d)] = __float2half_rn(rb);
        Mp16[(size_t)(2 * s + 1) * 512 + kperm(256 + d)] = __float2half_rn(-ra);
        return;
    }
    {
        bc[tid] = br[tid];
        bc[256 + tid] = bi[tid];
    }
}
#define PREP_BLOCKS (256 + 256 + 32 + 1024 + 4096 + 4096 + 256 + 256 + 1)

// ---------------- elementwise kernels ----------------
__global__ void ctx_partial_cvt_kernel(const float* __restrict__ h,
                                       float* __restrict__ part,
                                       __half* __restrict__ h16) {
    int tid = threadIdx.x;
    int d0 = tid * 4;
    int b = blockIdx.y, c = blockIdx.z;
    int p0 = kperm(d0);
    size_t row0 = (size_t)b * NSEQ + c * 32;
    const float* base = h + row0 * DIM;
    float s0 = 0.f, s1 = 0.f, s2 = 0.f, s3 = 0.f;
#pragma unroll 4
    for (int n = 0; n < 32; n++) {
        float4 v = *(const float4*)(base + (size_t)n * DIM + d0);
        s0 += v.x; s1 += v.y; s2 += v.z; s3 += v.w;
        __half* hr = h16 + (row0 + n) * DIM;
        *(__half2*)(hr + p0) = __floats2half2_rn(v.x, v.y);
        *(__half2*)(hr + p0 + 8) = __floats2half2_rn(v.z, v.w);
    }
    *(float4*)(part + (size_t)(b * 128 + c) * DIM + d0) = make_float4(s0, s1, s2, s3);
}

__global__ __launch_bounds__(1024) void ctxgate_kernel(
    const float* __restrict__ part,
    const float* __restrict__ w1, const float* __restrict__ b1,
    const float* __restrict__ gain, const float* __restrict__ beta,
    const float* __restrict__ w2, const float* __restrict__ b2,
    float* __restrict__ gamma)
{
    __shared__ float cs[DIM];
    __shared__ float tj[HIDN];
    int b = blockIdx.x, tid = threadIdx.x;
    int w = tid >> 5, l = tid & 31;

    float s = 0.f;
#pragma unroll
    for (int c = 0; c < 128; c++) s += part[(size_t)(b * 128 + c) * DIM + tid];
    cs[tid] = s * (1.f / (float)NSEQ);
    __syncthreads();

    float acc = 0.f;
#pragma unroll 8
    for (int it = 0; it < DIM / 32; it++) {
        int d = l + it * 32;
        acc += cs[d] * w1[d * HIDN + w];
    }
#pragma unroll
    for (int o = 16; o; o >>= 1) acc += __shfl_xor_sync(0xffffffffu, acc, o);
    if (l == 0) tj[w] = acc + b1[w];
    __syncthreads();

    if (tid < HIDN) {
        float v = tj[tid];
        float m = v;
#pragma unroll
        for (int o = 16; o; o >>= 1) m += __shfl_xor_sync(0xffffffffu, m, o);
        m *= (1.f / 32.f);
        float d = v - m;
        float var = d * d;
#pragma unroll
        for (int o = 16; o; o >>= 1) var += __shfl_xor_sync(0xffffffffu, var, o);
        var *= (1.f / 32.f);
        float tn = d * rsqrtf(var + 1e-5f) * gain[tid] + beta[tid];
        float si = tn / (1.f + expf(-tn));
        float p = si * w2[tid];
#pragma unroll
        for (int o = 16; o; o >>= 1) p += __shfl_xor_sync(0xffffffffu, p, o);
        if (tid == 0) gamma[b] = 1.f / (1.f + expf(-(p + b2[0])));
    }
}

__global__ void cvt_vot_kernel(const float* __restrict__ part, __half* __restrict__ out) {
    int i = (blockIdx.x * 256 + threadIdx.x) * 4;
    const int SZ = DIM * SS;
    float4 a = *(const float4*)(part + i);
    float4 b = *(const float4*)(part + SZ + i);
    float4 c = *(const float4*)(part + 2 * SZ + i);
    float4 d = *(const float4*)(part + 3 * SZ + i);
    float x = a.x + b.x + c.x + d.x;
    float y = a.y + b.y + c.y + d.y;
    float z = a.z + b.z + c.z + d.z;
    float w = a.w + b.w + c.w + d.w;
    int p0 = kperm(i);
    *(__half2*)(out + p0) = __floats2half2_rn(x, y);
    *(__half2*)(out + p0 + 8) = __floats2half2_rn(z, w);
}

// colsum of VOT: warp per d row.
__global__ void votsum_kernel(const __half* __restrict__ VOT16, float* __restrict__ S) {
    int wid = threadIdx.x >> 5, lane = threadIdx.x & 31;
    int d = blockIdx.x * 8 + wid;
    const __half2* r = (const __half2*)(VOT16 + (size_t)d * SS);
    float s = 0.f;
#pragma unroll
    for (int q = 0; q < 4; q++) {
        float2 v = __half22float2(r[lane + q * 32]);
        s += v.x + v.y;
    }
#pragma unroll
    for (int o = 16; o; o >>= 1) s += __shfl_xor_sync(0xffffffffu, s, o);
    if (lane == 0) S[d] = s;
}

// per-row attention affine factors: alpha = c1/D, beta = c0/D
__global__ void rowfac_kernel(const float* __restrict__ pinit, const float* __restrict__ gamma,
                              const float* __restrict__ rowssp, const float* __restrict__ ovsump,
                              float* __restrict__ alpha, float* __restrict__ beta) {
    int row = blockIdx.x * 256 + threadIdx.x;
    int b = row >> 12;
    float p = pinit[row] * (1.f - gamma[b]);
    float n2 = fmaxf(rowssp[row] + rowssp[NTOK + row], 1e-24f);
    float ovs = ovsump[row] + ovsump[NTOK + row];
    float c1 = (1.f - p) / n2;
    float c0 = p * (1.f / (float)DH);
    float D = c1 * ovs + (float)SS * c0 + 1e-8f;
    alpha[row] = c1 / D;
    beta[row] = c0 / D;
}

// mid LN: h1 = LN(h16 + ao16); writes ONLY fp16 kperm'd copy
__global__ void ln_add_mid_kernel(const __half* __restrict__ a, const __half* __restrict__ bsrc,
                                  const float* __restrict__ g, const float* __restrict__ beta,
                                  __half* __restrict__ outr) {
    size_t off = (size_t)blockIdx.x * DIM;
    int tid = threadIdx.x;
    float v[4];
    float s = 0.f;
#pragma unroll
    for (int q = 0; q < 4; q++) {
        int i = tid + q * 256;
        v[q] = __half2float(a[off + kperm(i)]) + __half2float(bsrc[off + i]);
        s += v[q];
    }
    float mu = block_sum_256(s) * (1.f / (float)DIM);
    float s2 = 0.f;
#pragma unroll
    for (int q = 0; q < 4; q++) {
        float d = v[q] - mu;
        s2 += d * d;
    }
    float var = block_sum_256(s2) * (1.f / (float)DIM);
    float inv = rsqrtf(var + 1e-5f);
#pragma unroll
    for (int q = 0; q < 4; q++) {
        int i = tid + q * 256;
        float o = (v[q] - mu) * inv * g[i] + beta[i];
        outr[off + kperm(i)] = __float2half_rn(o);
    }
}

// final LN: out = LN(h1r16[kperm] + ff216)
__global__ void ln_add_final_kernel(const __half* __restrict__ a, const __half* __restrict__ bsrc,
                                    const float* __restrict__ g, const float* __restrict__ beta,
                                    float* __restrict__ out) {
    size_t off = (size_t)blockIdx.x * DIM;
    int tid = threadIdx.x;
    float v[4];
    float s = 0.f;
#pragma unroll
    for (int q = 0; q < 4; q++) {
        int i = tid + q * 256;
        v[q] = __half2float(a[off + kperm(i)]) + __half2float(bsrc[off + i]);
        s += v[q];
    }
    float mu = block_sum_256(s) * (1.f / (float)DIM);
    float s2 = 0.f;
#pragma unroll
    for (int q = 0; q < 4; q++) {
        float d = v[q] - mu;
        s2 += d * d;
    }
    float var = block_sum_256(s2) * (1.f / (float)DIM);
    float inv = rsqrtf(var + 1e-5f);
#pragma unroll
    for (int q = 0; q < 4; q++) {
        int i = tid + q * 256;
        out[off + i] = (v[q] - mu) * inv * g[i] + beta[i];
    }
}

// ---------------- launch ----------------
static inline void* symv(const void* s) {
    void* p = nullptr;
    cudaGetSymbolAddress(&p, s);
    return p;
}

extern "C" void kernel_launch(void* const* d_in, const int* in_sizes, int n_in,
                              void* d_out, int out_size) {
    const float* h     = (const float*)d_in[0];
    const float* Wr    = (const float*)d_in[1];
    const float* br    = (const float*)d_in[2];
    const float* Wi    = (const float*)d_in[3];
    const float* bi    = (const float*)d_in[4];
    const float* uw1   = (const float*)d_in[5];
    const float* ub1   = (const float*)d_in[6];
    const float* ug    = (const float*)d_in[7];
    const float* ubeta = (const float*)d_in[8];
    const float* uw2   = (const float*)d_in[9];
    const float* ub2   = (const float*)d_in[10];
    const float* gw1   = (const float*)d_in[11];
    const float* gb1   = (const float*)d_in[12];
    const float* gg    = (const float*)d_in[13];
    const float* gbeta = (const float*)d_in[14];
    const float* gw2   = (const float*)d_in[15];
    const float* gb2   = (const float*)d_in[16];
    const float* m_real= (const float*)d_in[17];
    const float* m_imag= (const float*)d_in[18];
    const float* values= (const float*)d_in[19];
    const float* ow    = (const float*)d_in[20];
    const float* ob    = (const float*)d_in[21];
    const float* n1g   = (const float*)d_in[22];
    const float* n1b   = (const float*)d_in[23];
    const float* n2g   = (const float*)d_in[24];
    const float* n2b   = (const float*)d_in[25];
    const float* fw1   = (const float*)d_in[26];
    const float* fb1   = (const float*)d_in[27];
    const float* fw2   = (const float*)d_in[28];
    const float* fb2   = (const float*)d_in[29];
    float* out = (float*)d_out;

    float* pinit = (float*)symv(g_pinit);
    float* gam   = (float*)symv(g_gamma);
    float* ctxp  = (float*)symv(g_ctxpart);
    float* rowssp= (float*)symv(g_rowsspart);
    float* ovsump= (float*)symv(g_ovsump);
    float* alpha = (float*)symv(g_alpha);
    float* beta  = (float*)symv(g_beta);
    float* votS  = (float*)symv(g_votS);
    float* bc    = (float*)symv(g_bc);
    float* VOTp  = (float*)symv(g_VOTpart);
    __half* h16    = (__half*)symv(g_h16);
    __half* psi16  = (__half*)symv(g_psi16);
    __half* ov16   = (__half*)symv(g_ov16);
    __half* h1r16  = (__half*)symv(g_h1r16);
    __half* ff116  = (__half*)symv(g_ff116);
    __half* ao16   = (__half*)symv(g_ao16);
    __half* ff216  = (__half*)symv(g_ff216);
    __half* WT16   = (__half*)symv(g_WT16);
    __half* uw1T16 = (__half*)symv(g_uw1T16);
    __half* Mp16   = (__half*)symv(g_Mp16);
    __half* owT16  = (__half*)symv(g_owT16);
    __half* val16  = (__half*)symv(g_val16);
    __half* VOT16  = (__half*)symv(g_VOT16);
    __half* fw1T16 = (__half*)symv(g_fw1T16);
    __half* fw2T16 = (__half*)symv(g_fw2T16);

    const int smBIG  = (128 + 256) * 128 * 4;   // 196608
    const int smBIG1 = (128 + 128) * 128 * 4;   // 131072
    const int smGATE = (128 + 32) * 64 * 6;     // 61440
    cudaFuncSetAttribute(hgemm_big<256, false, 1, true >, cudaFuncAttributeMaxDynamicSharedMemorySize, smBIG);
    cudaFuncSetAttribute(hgemm_big<256, false, 3, false>, cudaFuncAttributeMaxDynamicSharedMemorySize, smBIG);
    cudaFuncSetAttribute(hgemm_big<256, false, 4, true >, cudaFuncAttributeMaxDynamicSharedMemorySize, smBIG);
    cudaFuncSetAttribute(hgemm_big<256, false, 5, false>, cudaFuncAttributeMaxDynamicSharedMemorySize, smBIG);
    cudaFuncSetAttribute(hgemm_big<256, true,  1, false>, cudaFuncAttributeMaxDynamicSharedMemorySize, smBIG);
    cudaFuncSetAttribute(hgemm_big<128, false, 2, false>, cudaFuncAttributeMaxDynamicSharedMemorySize, smBIG1);
    cudaFuncSetAttribute(hgemm_gate, cudaFuncAttributeMaxDynamicSharedMemorySize, smGATE);

    // fork-join streams/events (created once, outside capture on first call)
    static cudaStream_t s1 = nullptr, s2 = nullptr;
    static cudaEvent_t evEntry = nullptr, evPrep = nullptr, evCtx = nullptr,
                       evGate = nullptr, evVot = nullptr;
    if (!s1) {
        cudaStreamCreateWithFlags(&s1, cudaStreamNonBlocking);
        cudaStreamCreateWithFlags(&s2, cudaStreamNonBlocking);
        cudaEventCreateWithFlags(&evEntry, cudaEventDisableTiming);
        cudaEventCreateWithFlags(&evPrep, cudaEventDisableTiming);
        cudaEventCreateWithFlags(&evCtx, cudaEventDisableTiming);
        cudaEventCreateWithFlags(&evGate, cudaEventDisableTiming);
        cudaEventCreateWithFlags(&evVot, cudaEventDisableTiming);
    }

    dim3 thr(256);

    // fork s2: weight prep + VOT chain + colsum
    cudaEventRecord(evEntry, 0);
    cudaStreamWaitEvent(s2, evEntry, 0);
    prep_kernel<<<PREP_BLOCKS, thr, 0, s2>>>(Wr, Wi, uw1, ow, fw1, fw2, values,
                                             m_real, m_imag, br, bi,
                                             WT16, uw1T16, owT16, fw1T16, fw2T16,
                                             val16, Mp16, bc);
    cudaEventRecord(evPrep, s2);
    hgemm_big<256, false, 3, false><<<dim3(1, 8, 4), thr, smBIG, s2>>>(
        owT16, val16, nullptr, VOTp, nullptr, nullptr, nullptr, nullptr,
        DIM, SS, (size_t)DIM * SS);
    cvt_vot_kernel<<<DIM * SS / 1024, thr, 0, s2>>>(VOTp, VOT16);
    votsum_kernel<<<DIM / 8, thr, 0, s2>>>(VOT16, votS);
    cudaEventRecord(evVot, s2);

    // main: ctx partials + h -> h16 (overlaps prep)
    ctx_partial_cvt_kernel<<<dim3(1, BB, 128), thr>>>(h, ctxp, h16);
    cudaEventRecord(evCtx, 0);

    // s1: gamma gate + uncertainty gate (overlap psi/ov on main)
    cudaStreamWaitEvent(s1, evCtx, 0);
    cudaStreamWaitEvent(s1, evPrep, 0);
    ctxgate_kernel<<<BB, 1024, 0, s1>>>(ctxp, gw1, gb1, gg, gbeta, gw2, gb2, gam);
    hgemm_gate<<<dim3(1, 128), thr, smGATE, s1>>>(h16, uw1T16, ub1, ug, ubeta, uw2, ub2,
                                                  pinit, 0.95f, DIM);
    cudaEventRecord(evGate, s1);

    // main: psi (kperm'd + rowss partials) -> ov (overlap + ovsum partials)
    cudaStreamWaitEvent(0, evPrep, 0);
    hgemm_big<256, false, 1, true><<<dim3(2, 128), thr, smBIG>>>(
        h16, WT16, bc, psi16, rowssp, nullptr, nullptr, nullptr, DIM, 512, 0);
    hgemm_big<256, false, 4, true><<<dim3(2, 128), thr, smBIG>>>(
        psi16, Mp16, nullptr, ov16, ovsump, nullptr, nullptr, nullptr, 512, SS, 0);

    // join gate, then per-row attention factors
    cudaStreamWaitEvent(0, evGate, 0);
    rowfac_kernel<<<NTOK / 256, thr>>>(pinit, gam, rowssp, ovsump, alpha, beta);

    // join VOT, then ao = alpha*(ov @ VOT^T) + beta*S + ob   (fp16 plain)
    cudaStreamWaitEvent(0, evVot, 0);
    hgemm_big<256, false, 5, false><<<dim3(4, 128), thr, smBIG>>>(
        ov16, VOT16, ob, ao16, nullptr, alpha, beta, votS, SS, DIM, 0);

    // h1 = LN(h16 + ao16) -> fp16 kperm'd only
    ln_add_mid_kernel<<<NTOK, 256>>>(h16, ao16, n1g, n1b, h1r16);

    // FFN
    hgemm_big<256, true, 1, false><<<dim3(16, 128), thr, smBIG>>>(
        h1r16, fw1T16, fb1, ff116, nullptr, nullptr, nullptr, nullptr, DIM, DFF, 0);
    hgemm_big<128, false, 2, false><<<dim3(8, 128), thr, smBIG1>>>(
        ff116, fw2T16, fb2, ff216, nullptr, nullptr, nullptr, nullptr, DFF, DIM, 0);

    // out = LN(h1 + ff2)
    ln_add_final_kernel<<<NTOK, 256>>>(h1r16, ff216, n2g, n2b, out);
}

// round 16
// speedup vs baseline: 1.1379x; 1.0038x over previous
#include <cuda_runtime.h>
#include <cuda_fp16.h>
#include <math.h>
#include <stdint.h>

// ---------------- problem constants ----------------
#define BB    4
#define NSEQ  4096
#define NTOK  16384        // BB*NSEQ
#define DIM   1024
#define DH    256
#define SS    256
#define HIDN  32
#define DFF   4096

// ---------------- scratch (device globals: allowed) ----------------
__device__ float g_pinit[NTOK];
__device__ float g_gamma[BB];
__device__ float g_ctxpart[BB * 128 * DIM];
__device__ float g_rowsspart[2 * NTOK];   // psi sum-of-squares partials
__device__ float g_ovsump[2 * NTOK];      // overlap-sum partials
__device__ float g_alpha[NTOK];           // attn row scale (c1/D)
__device__ float g_beta[NTOK];            // attn row offset scale (c0/D)
__device__ float g_votS[DIM];             // colsum of VOT
__device__ float g_bc[512];               // [br | bi]
__device__ float g_VOTpart[4 * DIM * SS]; // split-K fp32 partials
// fp16 GEMM operands (kperm'd where used as GEMM input)
__device__ __half g_h16[NTOK * DIM];
__device__ __half g_psi16[NTOK * 512];    // unnormalized [pr|pi]
__device__ __half g_ov16[NTOK * SS];      // overlap, kperm'd on s
__device__ __half g_h1r16[NTOK * DIM];    // h1, fp16, kperm'd
__device__ __half g_ff116[NTOK * DFF];
__device__ __half g_ao16[NTOK * DIM];     // plain fp16
__device__ __half g_ff216[NTOK * DIM];    // plain fp16
__device__ __half g_WT16[512 * DIM];
__device__ __half g_uw1T16[HIDN * DIM];
__device__ __half g_Mp16[512 * 512];      // INTERLEAVED: row 2s=[Mr|Mi], 2s+1=[Mi|-Mr]
__device__ __half g_owT16[DIM * DIM];
__device__ __half g_val16[SS * DIM];
__device__ __half g_VOT16[DIM * SS];
__device__ __half g_fw1T16[DFF * DIM];
__device__ __half g_fw2T16[DIM * DFF];

// ---------------- helpers ----------------
__device__ __forceinline__ int kperm(int k) {
    int r = k & 31;
    int t = (r >> 1) & 3, w = r >> 4, hh = (r >> 3) & 1, j = r & 1;
    return (k & ~31) | (t << 3) | (w << 2) | (hh << 1) | j;
}

__device__ __forceinline__ float gelu_exact(float x) {
    return 0.5f * x * (1.0f + erff(x * 0.7071067811865475f));
}

__device__ __forceinline__ float block_sum_256(float v) {
    __shared__ float sh[8];
    int lane = threadIdx.x & 31, w = threadIdx.x >> 5;
#pragma unroll
    for (int o = 16; o; o >>= 1) v += __shfl_xor_sync(0xffffffffu, v, o);
    if (lane == 0) sh[w] = v;
    __syncthreads();
    float r = (lane < 8) ? sh[lane] : 0.f;
    if (w == 0) {
#pragma unroll
        for (int o = 4; o; o >>= 1) r += __shfl_xor_sync(0xffffffffu, r, o);
        if (lane == 0) sh[0] = r;
    }
    __syncthreads();
    float out = sh[0];
    __syncthreads();
    return out;
}

__device__ __forceinline__ uint32_t smem_u32(const void* p) {
    return (uint32_t)__cvta_generic_to_shared(p);
}
__device__ __forceinline__ void cp16(uint32_t dst, const void* src) {
    asm volatile("cp.async.cg.shared.global [%0], [%1], 16;" :: "r"(dst), "l"(src));
}
__device__ __forceinline__ void cp_commit() { asm volatile("cp.async.commit_group;"); }
template <int N>
__device__ __forceinline__ void cp_wait() { asm volatile("cp.async.wait_group %0;" :: "n"(N)); }

#define MMA_F16(d, a0, a1, a2, a3, b0, b1) \
    asm volatile( \
        "mma.sync.aligned.m16n8k16.row.col.f32.f16.f16.f32 " \
        "{%0,%1,%2,%3}, {%4,%5,%6,%7}, {%8,%9}, {%0,%1,%2,%3};" \
        : "+f"((d)[0]), "+f"((d)[1]), "+f"((d)[2]), "+f"((d)[3]) \
        : "r"(a0), "r"(a1), "r"(a2), "r"(a3), "r"(b0), "r"(b1))

// ============================================================
// BIG fp16 GEMM: 128 x BN CTA tile, 8 warps, BK = 64 slabs,
// 4-stage cp.async pipeline, prefetch distance 2, ONE sync per 64-k step.
// SMEM rows = 64 halfs (128 B); chunk swizzle p = c ^ ((row&1)<<2) makes
// both cp.async writes and LDS.128 fragment reads bank-conflict-free.
// OMODE: 1 fp16 kperm'd, 2 fp16 plain, 3 fp32 split-K partial,
//        4 overlap: col pairs (re,im) -> ov = re^2+im^2, fp16 kperm'd on s,
//        5 attn-affine: alpha_row*acc + beta_row*S_col + bias_col, fp16 plain.
// SUMSQ: per-row sum partials -> rowss[bx*NTOK+row].
// ============================================================
template <int BN>
__device__ __forceinline__ void load_slab_h(char* smem, int stage,
                                            const __half* gA, const __half* gB,
                                            int k0, int K, int tid) {
    constexpr int STAGE = (128 + BN) * 128;   // 64 halfs/row = 128 B
    uint32_t base = smem_u32(smem) + stage * STAGE;
#pragma unroll
    for (int i = 0; i < 4; i++) {             // A: 128 rows x 8 chunks
        int idx = tid + i * 256;
        int row = idx >> 3, c = idx & 7;
        int p = c ^ ((row & 1) << 2);
        cp16(base + (uint32_t)(row * 128 + p * 16),
             gA + (size_t)row * K + k0 + c * 8);
    }
    uint32_t bb = base + 128 * 128;
#pragma unroll
    for (int i = 0; i < BN / 32; i++) {       // B: BN rows x 8 chunks
        int idx = tid + i * 256;
        int row = idx >> 3, c = idx & 7;
        int p = c ^ ((row & 1) << 2);
        cp16(bb + (uint32_t)(row * 128 + p * 16),
             gB + (size_t)row * K + k0 + c * 8);
    }
}

template <int BN, bool GELU, int OMODE, bool SUMSQ>
__global__ __launch_bounds__(256, 1) void hgemm_big(
    const __half* __restrict__ A, const __half* __restrict__ B,
    const float* __restrict__ bias, void* __restrict__ Cv,
    float* __restrict__ rowss,
    const float* __restrict__ rowalpha, const float* __restrict__ rowbeta,
    const float* __restrict__ colS,
    int K, int Ntot, size_t zstride)
{
    extern __shared__ char smem[];
    constexpr int STAGE = (128 + BN) * 128;
    constexpr int NI = BN / 32;

    const int tid = threadIdx.x, wid = tid >> 5, lane = tid & 31;
    const int warp_m = (wid & 1) * 64;
    const int warp_n = (wid >> 1) * (BN / 4);
    const int g = lane >> 2, tg = lane & 3;
    const int psw = (g & 1) << 2;             // row-parity swizzle for fragments

    const int kchunk = K / gridDim.z;
    const __half* gA = A + (size_t)blockIdx.y * 128 * K + blockIdx.z * kchunk;
    const __half* gB = B + (size_t)blockIdx.x * BN * K + blockIdx.z * kchunk;
    const int NS = kchunk >> 6;               // 64-k slabs

    float acc[4][NI][4] = {};

    load_slab_h<BN>(smem, 0, gA, gB, 0, K, tid);  cp_commit();
    load_slab_h<BN>(smem, 1, gA, gB, 64, K, tid); cp_commit();

    for (int ks = 0; ks < NS; ks++) {
        if (ks + 2 < NS) {
            load_slab_h<BN>(smem, (ks + 2) & 3, gA, gB, (ks + 2) * 64, K, tid);
            cp_commit();
        }
        int rem = NS - 1 - ks;
        if (rem >= 2) cp_wait<2>();
        else if (rem == 1) cp_wait<1>();
        else cp_wait<0>();
        __syncthreads();

        const __half* As = (const __half*)(smem + (size_t)(ks & 3) * STAGE);
        const __half* Bs = As + 128 * 64;

#pragma unroll
        for (int h2 = 0; h2 < 2; h2++) {
            int chunk = h2 * 4 + tg;
            int ko = (chunk ^ psw) * 8;       // physical halfs offset in row
            uint4 aq[4][2];
#pragma unroll
            for (int mi = 0; mi < 4; mi++) {
                aq[mi][0] = *(const uint4*)(As + (warp_m + mi * 16 + g) * 64 + ko);
                aq[mi][1] = *(const uint4*)(As + (warp_m + mi * 16 + 8 + g) * 64 + ko);
            }
            uint4 bq[NI];
#pragma unroll
            for (int ni = 0; ni < NI; ni++)
                bq[ni] = *(const uint4*)(Bs + (warp_n + ni * 8 + g) * 64 + ko);

#pragma unroll
            for (int mi = 0; mi < 4; mi++) {
#pragma unroll
                for (int ni = 0; ni < NI; ni++) {
                    MMA_F16(acc[mi][ni], aq[mi][0].x, aq[mi][1].x, aq[mi][0].y, aq[mi][1].y,
                            bq[ni].x, bq[ni].y);
                    MMA_F16(acc[mi][ni], aq[mi][0].z, aq[mi][1].z, aq[mi][0].w, aq[mi][1].w,
                            bq[ni].z, bq[ni].w);
                }
            }
        }
        // no trailing sync (4-stage, prefetch distance 2)
    }
    __syncthreads();

    float ss[4][2];
    if (SUMSQ) {
#pragma unroll
        for (int mi = 0; mi < 4; mi++) { ss[mi][0] = 0.f; ss[mi][1] = 0.f; }
    }

#pragma unroll
    for (int mi = 0; mi < 4; mi++) {
        int r0 = blockIdx.y * 128 + warp_m + mi * 16 + g;
#pragma unroll
        for (int ni = 0; ni < NI; ni++) {
            int col = blockIdx.x * BN + warp_n + ni * 8 + 2 * tg;
            float bx = 0.f, by = 0.f;
            if ((OMODE == 1 || OMODE == 2 || OMODE == 5) && bias) {
                bx = bias[col]; by = bias[col + 1];
            }
#pragma unroll
            for (int half = 0; half < 2; half++) {
                int row = r0 + half * 8;
                float vx = acc[mi][ni][half * 2 + 0];
                float vy = acc[mi][ni][half * 2 + 1];
                if (OMODE == 4) {
                    float ov = vx * vx + vy * vy;
                    if (SUMSQ) ss[mi][half] += ov;
                    int s = col >> 1;
                    ((__half*)Cv)[(size_t)row * Ntot + kperm(s)] = __float2half_rn(ov);
                    continue;
                }
                if (OMODE == 5) {
                    float al = rowalpha[row], be = rowbeta[row];
                    vx = al * vx + be * colS[col] + bx;
                    vy = al * vy + be * colS[col + 1] + by;
                } else {
                    vx += bx; vy += by;
                }
                if (GELU) { vx = gelu_exact(vx); vy = gelu_exact(vy); }
                if (SUMSQ) ss[mi][half] += vx * vx + vy * vy;
                if (OMODE == 1) {
                    *(__half2*)((__half*)Cv + (size_t)row * Ntot + kperm(col)) =
                        __floats2half2_rn(vx, vy);
                } else if (OMODE == 2 || OMODE == 5) {
                    *(__half2*)((__half*)Cv + (size_t)row * Ntot + col) =
                        __floats2half2_rn(vx, vy);
                } else if (OMODE == 3) {
                    *(float2*)((float*)Cv + blockIdx.z * zstride + (size_t)row * Ntot + col) =
                        make_float2(vx, vy);
                }
            }
        }
    }

    if (SUMSQ) {
        float* red = (float*)smem;   // [128][4]
#pragma unroll
        for (int mi = 0; mi < 4; mi++) {
#pragma unroll
            for (int half = 0; half < 2; half++) {
                float v = ss[mi][half];
                v += __shfl_xor_sync(0xffffffffu, v, 1);
                v += __shfl_xor_sync(0xffffffffu, v, 2);
                if (tg == 0) {
                    int rl = warp_m + mi * 16 + half * 8 + g;
                    red[rl * 4 + (wid >> 1)] = v;
                }
            }
        }
        __syncthreads();
        if (tid < 128) {
            float tot = red[tid * 4] + red[tid * 4 + 1] + red[tid * 4 + 2] + red[tid * 4 + 3];
            rowss[blockIdx.x * NTOK + blockIdx.y * 128 + tid] = tot;
        }
    }
}

// ============================================================
// Gate GEMM (N = 32) with FUSED finish, 6-stage pipeline (BK = 32).
// ============================================================
__device__ __forceinline__ void load_slab_h32(char* smem, int stage,
                                              const __half* gA, const __half* gB,
                                              int k0, int K, int tid) {
    constexpr int STAGE = (128 + 32) * 64;
    uint32_t base = smem_u32(smem) + stage * STAGE;
#pragma unroll
    for (int i = 0; i < 2; i++) {
        int idx = tid + i * 256;
        int row = idx >> 2, c = idx & 3;
        cp16(base + (uint32_t)(row * 64 + c * 16),
             gA + (size_t)row * K + k0 + c * 8);
    }
    uint32_t bb = base + 128 * 64;
    if (tid < 128) {
        int row = tid >> 2, c = tid & 3;
        cp16(bb + (uint32_t)(row * 64 + c * 16),
             gB + (size_t)row * K + k0 + c * 8);
    }
}

__global__ __launch_bounds__(256) void hgemm_gate(
    const __half* __restrict__ A, const __half* __restrict__ B,
    const float* __restrict__ b1, const float* __restrict__ gain,
    const float* __restrict__ beta, const float* __restrict__ w2,
    const float* __restrict__ b2, float* __restrict__ pinit,
    float scale, int K)
{
    extern __shared__ char smem[];
    constexpr int STAGE = (128 + 32) * 64;

    const int tid = threadIdx.x, wid = tid >> 5, lane = tid & 31;
    const int warp_m = wid * 16;
    const int gg2 = lane >> 2, tg = lane & 3;

    const __half* gA = A + (size_t)blockIdx.y * 128 * K;
    const __half* gB = B;
    const int NS = K >> 5;

    float acc[4][4] = {};

#pragma unroll
    for (int s = 0; s < 5; s++) {
        load_slab_h32(smem, s, gA, gB, s * 32, K, tid);
        cp_commit();
    }

    for (int ks = 0; ks < NS; ks++) {
        if (ks + 5 < NS) {
            load_slab_h32(smem, (ks + 5) % 6, gA, gB, (ks + 5) * 32, K, tid);
            cp_commit();
        }
        int rem = NS - 1 - ks;
        if (rem >= 5) cp_wait<5>();
        else if (rem == 4) cp_wait<4>();
        else if (rem == 3) cp_wait<3>();
        else if (rem == 2) cp_wait<2>();
        else if (rem == 1) cp_wait<1>();
        else cp_wait<0>();
        __syncthreads();

        const __half* As = (const __half*)(smem + (size_t)(ks % 6) * STAGE);
        const __half* Bs = As + 128 * 32;

        uint4 alo = *(const uint4*)(As + (warp_m + gg2) * 32 + 8 * tg);
        uint4 ahi = *(const uint4*)(As + (warp_m + 8 + gg2) * 32 + 8 * tg);
        uint4 bq[4];
#pragma unroll
        for (int ni = 0; ni < 4; ni++)
            bq[ni] = *(const uint4*)(Bs + (ni * 8 + gg2) * 32 + 8 * tg);
#pragma unroll
        for (int ni = 0; ni < 4; ni++) {
            MMA_F16(acc[ni], alo.x, ahi.x, alo.y, ahi.y, bq[ni].x, bq[ni].y);
            MMA_F16(acc[ni], alo.z, ahi.z, alo.w, ahi.w, bq[ni].z, bq[ni].w);
        }
        __syncthreads();
    }

#pragma unroll
    for (int half = 0; half < 2; half++) {
        float vv[8];
        float sum = 0.f;
#pragma unroll
        for (int ni = 0; ni < 4; ni++) {
#pragma unroll
            for (int j = 0; j < 2; j++) {
                int col = ni * 8 + 2 * tg + j;
                float v = acc[ni][half * 2 + j] + b1[col];
                vv[ni * 2 + j] = v;
                sum += v;
            }
        }
        sum += __shfl_xor_sync(0xffffffffu, sum, 1);
        sum += __shfl_xor_sync(0xffffffffu, sum, 2);
        float m = sum * (1.f / 32.f);
        float s2 = 0.f;
#pragma unroll
        for (int q = 0; q < 8; q++) { float d = vv[q] - m; s2 += d * d; }
        s2 += __shfl_xor_sync(0xffffffffu, s2, 1);
        s2 += __shfl_xor_sync(0xffffffffu, s2, 2);
        float inv = rsqrtf(s2 * (1.f / 32.f) + 1e-5f);
        float p = 0.f;
#pragma unroll
        for (int ni = 0; ni < 4; ni++) {
#pragma unroll
            for (int j = 0; j < 2; j++) {
                int col = ni * 8 + 2 * tg + j;
                float tn = (vv[ni * 2 + j] - m) * inv * gain[col] + beta[col];
                float si = tn / (1.f + expf(-tn));
                p += si * w2[col];
            }
        }
        p += __shfl_xor_sync(0xffffffffu, p, 1);
        p += __shfl_xor_sync(0xffffffffu, p, 2);
        if (tg == 0) {
            int row = blockIdx.y * 128 + warp_m + half * 8 + gg2;
            pinit[row] = scale / (1.f + expf(-(p + b2[0])));
        }
    }
}

// ============================================================
// PREP megakernel (job table). All blocks 256 threads.
// ============================================================
__device__ __forceinline__ void transpose_tile(const float* in, __half* out,
                                               int R, int C, int lb, int tid) {
    __shared__ float t[32][33];
    int nbx = C >> 5;
    int bx = lb % nbx, by = lb / nbx;
    int c0 = bx * 32, r0 = by * 32;
    int x = tid & 31, y = tid >> 5;
#pragma unroll
    for (int dy = 0; dy < 32; dy += 8)
        t[y + dy][x] = in[(size_t)(r0 + y + dy) * C + c0 + x];
    __syncthreads();
#pragma unroll
    for (int dy = 0; dy < 32; dy += 8)
        out[(size_t)(c0 + y + dy) * R + kperm(r0 + x)] = __float2half_rn(t[x][y + dy]);
}

__global__ void prep_kernel(
    const float* __restrict__ Wr, const float* __restrict__ Wi,
    const float* __restrict__ uw1, const float* __restrict__ ow,
    const float* __restrict__ fw1, const float* __restrict__ fw2,
    const float* __restrict__ values,
    const float* __restrict__ mr, const float* __restrict__ mi,
    const float* __restrict__ br, const float* __restrict__ bi,
    __half* __restrict__ WT16, __half* __restrict__ uw1T16,
    __half* __restrict__ owT16, __half* __restrict__ fw1T16,
    __half* __restrict__ fw2T16, __half* __restrict__ val16,
    __half* __restrict__ Mp16, float* __restrict__ bc)
{
    int b = blockIdx.x, tid = threadIdx.x;
    if (b < 256) { transpose_tile(Wr, WT16, DIM, DH, b, tid); return; }
    b -= 256;
    if (b < 256) { transpose_tile(Wi, WT16 + 256 * DIM, DIM, DH, b, tid); return; }
    b -= 256;
    if (b < 32)  { transpose_tile(uw1, uw1T16, DIM, HIDN, b, tid); return; }
    b -= 32;
    if (b < 1024){ transpose_tile(ow, owT16, DIM, DIM, b, tid); return; }
    b -= 1024;
    if (b < 4096){ transpose_tile(fw1, fw1T16, DIM, DFF, b, tid); return; }
    b -= 4096;
    if (b < 4096){ transpose_tile(fw2, fw2T16, DFF, DIM, b, tid); return; }
    b -= 4096;
    if (b < 256) {
        int i = (b * 256 + tid) * 4;
        float4 v = *(const float4*)(values + i);
        int p0 = kperm(i);
        *(__half2*)(val16 + p0) = __floats2half2_rn(v.x, v.y);
        *(__half2*)(val16 + p0 + 8) = __floats2half2_rn(v.z, v.w);
        return;
    }
    b -= 256;
    if (b < 256) {
        // memnorm -> INTERLEAVED Mp: row 2s = [Mr|Mi], row 2s+1 = [Mi|-Mr]
        int s = b, d = tid;
        float a = mr[s * DH + d], bb2 = mi[s * DH + d];
        float tot = block_sum_256(a * a + bb2 * bb2);
        float inv = 1.f / fmaxf(sqrtf(tot), 1e-12f);
        float ra = a * inv, rb = bb2 * inv;
        Mp16[(size_t)(2 * s) * 512 + kperm(d)] = __float2half_rn(ra);
        Mp16[(size_t)(2 * s) * 512 + kperm(256 + d)] = __float2half_rn(rb);
        Mp16[(size_t)(2 * s + 1) * 512 + kperm(d)] = __float2half_rn(rb);
        Mp16[(size_t)(2 * s + 1) * 512 + kperm(256 + d)] = __float2half_rn(-ra);
        return;
    }
    {
        bc[tid] = br[tid];
        bc[256 + tid] = bi[tid];
    }
}
#define PREP_BLOCKS (256 + 256 + 32 + 1024 + 4096 + 4096 + 256 + 256 + 1)

// ---------------- elementwise kernels ----------------
__global__ void ctx_partial_cvt_kernel(const float* __restrict__ h,
                                       float* __restrict__ part,
                                       __half* __restrict__ h16) {
    int tid = threadIdx.x;
    int d0 = tid * 4;
    int b = blockIdx.y, c = blockIdx.z;
    int p0 = kperm(d0);
    size_t row0 = (size_t)b * NSEQ + c * 32;
    const float* base = h + row0 * DIM;
    float s0 = 0.f, s1 = 0.f, s2 = 0.f, s3 = 0.f;
#pragma unroll 4
    for (int n = 0; n < 32; n++) {
        float4 v = *(const float4*)(base + (size_t)n * DIM + d0);
        s0 += v.x; s1 += v.y; s2 += v.z; s3 += v.w;
        __half* hr = h16 + (row0 + n) * DIM;
        *(__half2*)(hr + p0) = __floats2half2_rn(v.x, v.y);
        *(__half2*)(hr + p0 + 8) = __floats2half2_rn(v.z, v.w);
    }
    *(float4*)(part + (size_t)(b * 128 + c) * DIM + d0) = make_float4(s0, s1, s2, s3);
}

__global__ __launch_bounds__(1024) void ctxgate_kernel(
    const float* __restrict__ part,
    const float* __restrict__ w1, const float* __restrict__ b1,
    const float* __restrict__ gain, const float* __restrict__ beta,
    const float* __restrict__ w2, const float* __restrict__ b2,
    float* __restrict__ gamma)
{
    __shared__ float cs[DIM];
    __shared__ float tj[HIDN];
    int b = blockIdx.x, tid = threadIdx.x;
    int w = tid >> 5, l = tid & 31;

    float s = 0.f;
#pragma unroll
    for (int c = 0; c < 128; c++) s += part[(size_t)(b * 128 + c) * DIM + tid];
    cs[tid] = s * (1.f / (float)NSEQ);
    __syncthreads();

    float acc = 0.f;
#pragma unroll 8
    for (int it = 0; it < DIM / 32; it++) {
        int d = l + it * 32;
        acc += cs[d] * w1[d * HIDN + w];
    }
#pragma unroll
    for (int o = 16; o; o >>= 1) acc += __shfl_xor_sync(0xffffffffu, acc, o);
    if (l == 0) tj[w] = acc + b1[w];
    __syncthreads();

    if (tid < HIDN) {
        float v = tj[tid];
        float m = v;
#pragma unroll
        for (int o = 16; o; o >>= 1) m += __shfl_xor_sync(0xffffffffu, m, o);
        m *= (1.f / 32.f);
        float d = v - m;
        float var = d * d;
#pragma unroll
        for (int o = 16; o; o >>= 1) var += __shfl_xor_sync(0xffffffffu, var, o);
        var *= (1.f / 32.f);
        float tn = d * rsqrtf(var + 1e-5f) * gain[tid] + beta[tid];
        float si = tn / (1.f + expf(-tn));
        float p = si * w2[tid];
#pragma unroll
        for (int o = 16; o; o >>= 1) p += __shfl_xor_sync(0xffffffffu, p, o);
        if (tid == 0) gamma[b] = 1.f / (1.f + expf(-(p + b2[0])));
    }
}

__global__ void cvt_vot_kernel(const float* __restrict__ part, __half* __restrict__ out) {
    int i = (blockIdx.x * 256 + threadIdx.x) * 4;
    const int SZ = DIM * SS;
    float4 a = *(const float4*)(part + i);
    float4 b = *(const float4*)(part + SZ + i);
    float4 c = *(const float4*)(part + 2 * SZ + i);
    float4 d = *(const float4*)(part + 3 * SZ + i);
    float x = a.x + b.x + c.x + d.x;
    float y = a.y + b.y + c.y + d.y;
    float z = a.z + b.z + c.z + d.z;
    float w = a.w + b.w + c.w + d.w;
    int p0 = kperm(i);
    *(__half2*)(out + p0) = __floats2half2_rn(x, y);
    *(__half2*)(out + p0 + 8) = __floats2half2_rn(z, w);
}

// colsum of VOT: warp per d row.
__global__ void votsum_kernel(const __half* __restrict__ VOT16, float* __restrict__ S) {
    int wid = threadIdx.x >> 5, lane = threadIdx.x & 31;
    int d = blockIdx.x * 8 + wid;
    const __half2* r = (const __half2*)(VOT16 + (size_t)d * SS);
    float s = 0.f;
#pragma unroll
    for (int q = 0; q < 4; q++) {
        float2 v = __half22float2(r[lane + q * 32]);
        s += v.x + v.y;
    }
#pragma unroll
    for (int o = 16; o; o >>= 1) s += __shfl_xor_sync(0xffffffffu, s, o);
    if (lane == 0) S[d] = s;
}

// per-row attention affine factors: alpha = c1/D, beta = c0/D
__global__ void rowfac_kernel(const float* __restrict__ pinit, const float* __restrict__ gamma,
                              const float* __restrict__ rowssp, const float* __restrict__ ovsump,
                              float* __restrict__ alpha, float* __restrict__ beta) {
    int row = blockIdx.x * 256 + threadIdx.x;
    int b = row >> 12;
    float p = pinit[row] * (1.f - gamma[b]);
    float n2 = fmaxf(rowssp[row] + rowssp[NTOK + row], 1e-24f);
    float ovs = ovsump[row] + ovsump[NTOK + row];
    float c1 = (1.f - p) / n2;
    float c0 = p * (1.f / (float)DH);
    float D = c1 * ovs + (float)SS * c0 + 1e-8f;
    alpha[row] = c1 / D;
    beta[row] = c0 / D;
}

// mid LN: h1 = LN(h16 + ao16); writes ONLY fp16 kperm'd copy.
// Vectorized: each thread owns 4 consecutive columns (d0 = tid*4).
__global__ void ln_add_mid_kernel(const __half* __restrict__ a, const __half* __restrict__ bsrc,
                                  const float* __restrict__ g, const float* __restrict__ beta,
                                  __half* __restrict__ outr) {
    size_t off = (size_t)blockIdx.x * DIM;
    int tid = threadIdx.x;
    int d0 = tid * 4;
    int p0 = kperm(d0);
    float2 a01 = __half22float2(*(const __half2*)(a + off + p0));
    float2 a23 = __half22float2(*(const __half2*)(a + off + p0 + 8));
    float2 b01 = __half22float2(*(const __half2*)(bsrc + off + d0));
    float2 b23 = __half22float2(*(const __half2*)(bsrc + off + d0 + 2));
    float v[4];
    v[0] = a01.x + b01.x; v[1] = a01.y + b01.y;
    v[2] = a23.x + b23.x; v[3] = a23.y + b23.y;
    float s = v[0] + v[1] + v[2] + v[3];
    float mu = block_sum_256(s) * (1.f / (float)DIM);
    float s2 = 0.f;
#pragma unroll
    for (int q = 0; q < 4; q++) {
        float d = v[q] - mu;
        s2 += d * d;
    }
    float var = block_sum_256(s2) * (1.f / (float)DIM);
    float inv = rsqrtf(var + 1e-5f);
    float4 gv = *(const float4*)(g + d0);
    float4 bv = *(const float4*)(beta + d0);
    float o0 = (v[0] - mu) * inv * gv.x + bv.x;
    float o1 = (v[1] - mu) * inv * gv.y + bv.y;
    float o2 = (v[2] - mu) * inv * gv.z + bv.z;
    float o3 = (v[3] - mu) * inv * gv.w + bv.w;
    *(__half2*)(outr + off + p0) = __floats2half2_rn(o0, o1);
    *(__half2*)(outr + off + p0 + 8) = __floats2half2_rn(o2, o3);
}

// final LN: out = LN(h1r16[kperm] + ff216). Vectorized like mid.
__global__ void ln_add_final_kernel(const __half* __restrict__ a, const __half* __restrict__ bsrc,
                                    const float* __restrict__ g, const float* __restrict__ beta,
                                    float* __restrict__ out) {
    size_t off = (size_t)blockIdx.x * DIM;
    int tid = threadIdx.x;
    int d0 = tid * 4;
    int p0 = kperm(d0);
    float2 a01 = __half22float2(*(const __half2*)(a + off + p0));
    float2 a23 = __half22float2(*(const __half2*)(a + off + p0 + 8));
    float2 b01 = __half22float2(*(const __half2*)(bsrc + off + d0));
    float2 b23 = __half22float2(*(const __half2*)(bsrc + off + d0 + 2));
    float v[4];
    v[0] = a01.x + b01.x; v[1] = a01.y + b01.y;
    v[2] = a23.x + b23.x; v[3] = a23.y + b23.y;
    float s = v[0] + v[1] + v[2] + v[3];
    float mu = block_sum_256(s) * (1.f / (float)DIM);
    float s2 = 0.f;
#pragma unroll
    for (int q = 0; q < 4; q++) {
        float d = v[q] - mu;
        s2 += d * d;
    }
    float var = block_sum_256(s2) * (1.f / (float)DIM);
    float inv = rsqrtf(var + 1e-5f);
    float4 gv = *(const float4*)(g + d0);
    float4 bv = *(const float4*)(beta + d0);
    float4 o;
    o.x = (v[0] - mu) * inv * gv.x + bv.x;
    o.y = (v[1] - mu) * inv * gv.y + bv.y;
    o.z = (v[2] - mu) * inv * gv.z + bv.z;
    o.w = (v[3] - mu) * inv * gv.w + bv.w;
    *(float4*)(out + off + d0) = o;
}

// ---------------- launch ----------------
static inline void* symv(const void* s) {
    void* p = nullptr;
    cudaGetSymbolAddress(&p, s);
    return p;
}

extern "C" void kernel_launch(void* const* d_in, const int* in_sizes, int n_in,
                              void* d_out, int out_size) {
    const float* h     = (const float*)d_in[0];
    const float* Wr    = (const float*)d_in[1];
    const float* br    = (const float*)d_in[2];
    const float* Wi    = (const float*)d_in[3];
    const float* bi    = (const float*)d_in[4];
    const float* uw1   = (const float*)d_in[5];
    const float* ub1   = (const float*)d_in[6];
    const float* ug    = (const float*)d_in[7];
    const float* ubeta = (const float*)d_in[8];
    const float* uw2   = (const float*)d_in[9];
    const float* ub2   = (const float*)d_in[10];
    const float* gw1   = (const float*)d_in[11];
    const float* gb1   = (const float*)d_in[12];
    const float* gg    = (const float*)d_in[13];
    const float* gbeta = (const float*)d_in[14];
    const float* gw2   = (const float*)d_in[15];
    const float* gb2   = (const float*)d_in[16];
    const float* m_real= (const float*)d_in[17];
    const float* m_imag= (const float*)d_in[18];
    const float* values= (const float*)d_in[19];
    const float* ow    = (const float*)d_in[20];
    const float* ob    = (const float*)d_in[21];
    const float* n1g   = (const float*)d_in[22];
    const float* n1b   = (const float*)d_in[23];
    const float* n2g   = (const float*)d_in[24];
    const float* n2b   = (const float*)d_in[25];
    const float* fw1   = (const float*)d_in[26];
    const float* fb1   = (const float*)d_in[27];
    const float* fw2   = (const float*)d_in[28];
    const float* fb2   = (const float*)d_in[29];
    float* out = (float*)d_out;

    float* pinit = (float*)symv(g_pinit);
    float* gam   = (float*)symv(g_gamma);
    float* ctxp  = (float*)symv(g_ctxpart);
    float* rowssp= (float*)symv(g_rowsspart);
    float* ovsump= (float*)symv(g_ovsump);
    float* alpha = (float*)symv(g_alpha);
    float* beta  = (float*)symv(g_beta);
    float* votS  = (float*)symv(g_votS);
    float* bc    = (float*)symv(g_bc);
    float* VOTp  = (float*)symv(g_VOTpart);
    __half* h16    = (__half*)symv(g_h16);
    __half* psi16  = (__half*)symv(g_psi16);
    __half* ov16   = (__half*)symv(g_ov16);
    __half* h1r16  = (__half*)symv(g_h1r16);
    __half* ff116  = (__half*)symv(g_ff116);
    __half* ao16   = (__half*)symv(g_ao16);
    __half* ff216  = (__half*)symv(g_ff216);
    __half* WT16   = (__half*)symv(g_WT16);
    __half* uw1T16 = (__half*)symv(g_uw1T16);
    __half* Mp16   = (__half*)symv(g_Mp16);
    __half* owT16  = (__half*)symv(g_owT16);
    __half* val16  = (__half*)symv(g_val16);
    __half* VOT16  = (__half*)symv(g_VOT16);
    __half* fw1T16 = (__half*)symv(g_fw1T16);
    __half* fw2T16 = (__half*)symv(g_fw2T16);

    const int smBIG  = (128 + 256) * 128 * 4;   // 196608
    const int smBIG1 = (128 + 128) * 128 * 4;   // 131072
    const int smGATE = (128 + 32) * 64 * 6;     // 61440
    cudaFuncSetAttribute(hgemm_big<256, false, 1, true >, cudaFuncAttributeMaxDynamicSharedMemorySize, smBIG);
    cudaFuncSetAttribute(hgemm_big<256, false, 3, false>, cudaFuncAttributeMaxDynamicSharedMemorySize, smBIG);
    cudaFuncSetAttribute(hgemm_big<256, false, 4, true >, cudaFuncAttributeMaxDynamicSharedMemorySize, smBIG);
    cudaFuncSetAttribute(hgemm_big<256, false, 5, false>, cudaFuncAttributeMaxDynamicSharedMemorySize, smBIG);
    cudaFuncSetAttribute(hgemm_big<256, true,  1, false>, cudaFuncAttributeMaxDynamicSharedMemorySize, smBIG);
    cudaFuncSetAttribute(hgemm_big<128, false, 2, false>, cudaFuncAttributeMaxDynamicSharedMemorySize, smBIG1);
    cudaFuncSetAttribute(hgemm_gate, cudaFuncAttributeMaxDynamicSharedMemorySize, smGATE);

    // fork-join streams/events (created once, outside capture on first call)
    static cudaStream_t s1 = nullptr, s2 = nullptr;
    static cudaEvent_t evEntry = nullptr, evPrep = nullptr, evCtx = nullptr,
                       evGate = nullptr, evVot = nullptr;
    if (!s1) {
        cudaStreamCreateWithFlags(&s1, cudaStreamNonBlocking);
        cudaStreamCreateWithFlags(&s2, cudaStreamNonBlocking);
        cudaEventCreateWithFlags(&evEntry, cudaEventDisableTiming);
        cudaEventCreateWithFlags(&evPrep, cudaEventDisableTiming);
        cudaEventCreateWithFlags(&evCtx, cudaEventDisableTiming);
        cudaEventCreateWithFlags(&evGate, cudaEventDisableTiming);
        cudaEventCreateWithFlags(&evVot, cudaEventDisableTiming);
    }

    dim3 thr(256);

    // fork s2: weight prep + VOT chain + colsum
    cudaEventRecord(evEntry, 0);
    cudaStreamWaitEvent(s2, evEntry, 0);
    prep_kernel<<<PREP_BLOCKS, thr, 0, s2>>>(Wr, Wi, uw1, ow, fw1, fw2, values,
                                             m_real, m_imag, br, bi,
                                             WT16, uw1T16, owT16, fw1T16, fw2T16,
                                             val16, Mp16, bc);
    cudaEventRecord(evPrep, s2);
    hgemm_big<256, false, 3, false><<<dim3(1, 8, 4), thr, smBIG, s2>>>(
        owT16, val16, nullptr, VOTp, nullptr, nullptr, nullptr, nullptr,
        DIM, SS, (size_t)DIM * SS);
    cvt_vot_kernel<<<DIM * SS / 1024, thr, 0, s2>>>(VOTp, VOT16);
    votsum_kernel<<<DIM / 8, thr, 0, s2>>>(VOT16, votS);
    cudaEventRecord(evVot, s2);

    // main: ctx partials + h -> h16 (overlaps prep)
    ctx_partial_cvt_kernel<<<dim3(1, BB, 128), thr>>>(h, ctxp, h16);
    cudaEventRecord(evCtx, 0);

    // s1: gamma gate + uncertainty gate (overlap psi/ov on main)
    cudaStreamWaitEvent(s1, evCtx, 0);
    cudaStreamWaitEvent(s1, evPrep, 0);
    ctxgate_kernel<<<BB, 1024, 0, s1>>>(ctxp, gw1, gb1, gg, gbeta, gw2, gb2, gam);
    hgemm_gate<<<dim3(1, 128), thr, smGATE, s1>>>(h16, uw1T16, ub1, ug, ubeta, uw2, ub2,
                                                  pinit, 0.95f, DIM);
    cudaEventRecord(evGate, s1);

    // main: psi (kperm'd + rowss partials) -> ov (overlap + ovsum partials)
    cudaStreamWaitEvent(0, evPrep, 0);
    hgemm_big<256, false, 1, true><<<dim3(2, 128), thr, smBIG>>>(
        h16, WT16, bc, psi16, rowssp, nullptr, nullptr, nullptr, DIM, 512, 0);
    hgemm_big<256, false, 4, true><<<dim3(2, 128), thr, smBIG>>>(
        psi16, Mp16, nullptr, ov16, ovsump, nullptr, nullptr, nullptr, 512, SS, 0);

    // join gate, then per-row attention factors
    cudaStreamWaitEvent(0, evGate, 0);
    rowfac_kernel<<<NTOK / 256, thr>>>(pinit, gam, rowssp, ovsump, alpha, beta);

    // join VOT, then ao = alpha*(ov @ VOT^T) + beta*S + ob   (fp16 plain)
    cudaStreamWaitEvent(0, evVot, 0);
    hgemm_big<256, false, 5, false><<<dim3(4, 128), thr, smBIG>>>(
        ov16, VOT16, ob, ao16, nullptr, alpha, beta, votS, SS, DIM, 0);

    // h1 = LN(h16 + ao16) -> fp16 kperm'd only
    ln_add_mid_kernel<<<NTOK, 256>>>(h16, ao16, n1g, n1b, h1r16);

    // FFN
    hgemm_big<256, true, 1, false><<<dim3(16, 128), thr, smBIG>>>(
        h1r16, fw1T16, fb1, ff116, nullptr, nullptr, nullptr, nullptr, DIM, DFF, 0);
    hgemm_big<128, false, 2, false><<<dim3(8, 128), thr, smBIG1>>>(
        ff116, fw2T16, fb2, ff216, nullptr, nullptr, nullptr, nullptr, DFF, DIM, 0);

    // out = LN(h1 + ff2)
    ln_add_final_kernel<<<NTOK, 256>>>(h1r16, ff216, n2g, n2b, out);
}